// round 8
// baseline (speedup 1.0000x reference)
#include <cuda_runtime.h>
#include <cstdint>

using ull = unsigned long long;

__device__ __forceinline__ float2 unpack2(ull v) {
    float2 f; asm("mov.b64 {%0,%1},%2;" : "=f"(f.x), "=f"(f.y) : "l"(v)); return f;
}
__device__ __forceinline__ void fma2(ull& d, ull a, ull b) {
    asm("fma.rn.f32x2 %0,%1,%2,%0;" : "+l"(d) : "l"(a), "l"(b));
}

// Ping-pong activation buffers; __device__ globals are the sanctioned scratch.
__device__ float g_bufA[33554432];
__device__ float g_bufB[33554432];

// ---------------------------------------------------------------------------
// First conv: non-overlapping 4x4 patches -> 64 ch + ReLU.
// ---------------------------------------------------------------------------
__global__ void __launch_bounds__(256) first_conv(
    const float* __restrict__ in, const float* __restrict__ fw,
    const float* __restrict__ bias, float* __restrict__ out) {
    __shared__ float sIn[16 * 17];
    __shared__ float sW[1024];
    __shared__ float sB[64];
    const int tid = threadIdx.x;
    for (int j = tid; j < 1024; j += 256) sW[j] = fw[j];
    if (tid < 64) sB[tid] = bias[tid];
    const int P0 = blockIdx.x * 16;
    if (tid < 64) {
        const int pix = tid >> 2, p = tid & 3;
        const int P = P0 + pix, b = P >> 12, x = (P >> 6) & 63, y = P & 63;
        float4 v = *reinterpret_cast<const float4*>(
            in + ((size_t)(b * 256 + 4 * x + p)) * 256 + 4 * y);
        sIn[pix * 17 + p * 4 + 0] = v.x;
        sIn[pix * 17 + p * 4 + 1] = v.y;
        sIn[pix * 17 + p * 4 + 2] = v.z;
        sIn[pix * 17 + p * 4 + 3] = v.w;
    }
    __syncthreads();
    const int c = tid & 63, pq = tid >> 6;
    float acc[4] = {sB[c], sB[c], sB[c], sB[c]};
#pragma unroll
    for (int i = 0; i < 16; i++) {
        const float w = sW[i * 64 + c];
#pragma unroll
        for (int j = 0; j < 4; j++) acc[j] += sIn[(pq * 4 + j) * 17 + i] * w;
    }
#pragma unroll
    for (int j = 0; j < 4; j++)
        out[(size_t)(P0 + pq * 4 + j) * 64 + c] = fmaxf(acc[j], 0.0f);
}

// ---------------------------------------------------------------------------
// Node conv (levels 1..6).  Per node GEMM: M=B*H*H, K=256 (8 stages of 32),
// N=64.  NT=256 threads, MT=128 m-rows per block, 2 blocks/SM.
// sA: k-major [k][m] with col rotation (4mg+4k)&127 — STS at the 4-phase
// minimum, reads 1-phase.  Thread stages a 4m x 4k block: 4 coalesced
// LDG.128 -> 4 STS.128 (in-register transpose, no scalar stores).
// sW: {w,w} duplicated pairs at k*128 + ((c&7)>>1)*32 + (c>>3)*4 + (c&1)*2:
// reads are 4 x 1-phase LDS.128 per k.
// Inner loop per k: 1 A-LDS + 4 W-LDS + 16 FFMA2, zero packs.
// Microtile 4m x 8n, acc[2 m-pairs][8 c] FFMA2 accumulators.
// Double-buffered, one barrier per stage.
// ---------------------------------------------------------------------------
template <int NU, int NP, int HO>
__global__ void __launch_bounds__(256, 2) node_conv(
    const float* __restrict__ in, const float* __restrict__ fw,
    const float* __restrict__ bias, float* __restrict__ out) {
    constexpr int Bn = 128, C = 64, HI = 2 * HO, WI = 2 * HO, WO = HO;
    constexpr int M = Bn * HO * WO;
    constexpr int MT = 128;
    constexpr int ABUF = 32 * 128;  // one stage of A (k-major, rotated)
    constexpr int WBUF = 32 * 128;  // one stage of dup W

    extern __shared__ float smem[];
    float* sA0 = smem;             // 2 * ABUF
    float* sW0 = smem + 2 * ABUF;  // 2 * WBUF

    const int tid = threadIdx.x;
    const int node = blockIdx.y;
    const int u = node / NU, v = node % NU;
    const int pu = (NP < NU) ? (u >> 1) : u;
    const int pv = (NP < NU) ? (v >> 1) : v;
    const float* inN = in + (size_t)(pu * NP + pv) * Bn * HI * WI * C;
    const float* fN = fw + (size_t)node * 4 * C * C;
    const float* bN = bias + (size_t)node * C;
    const int m0 = blockIdx.x * MT;

    const int kslot = tid & 7;  // owns k = 4*kslot..+3 within a stage
    const int mg = tid >> 3;    // owns m-rows 4*mg..4*mg+3 (also compute pg)

    unsigned aoff[4];
#pragma unroll
    for (int i = 0; i < 4; i++) {
        const int m = m0 + mg * 4 + i;
        const int b = m / (HO * WO);
        const int hw = m - b * HO * WO;
        const int h = hw / WO, w = hw - h * WO;
        aoff[i] = (unsigned)((((b * HI + 2 * h) * WI + 2 * w) * C) + kslot * 4);
    }

    float4 aR[4], wR[2];
    auto LDG = [&](int s) {
        const int x = s >> 2, y = (s >> 1) & 1, cb = (s & 1) * 32;
        const unsigned soff = (unsigned)((x * WI + y) * C + cb);
#pragma unroll
        for (int i = 0; i < 4; i++)
            aR[i] = *reinterpret_cast<const float4*>(inN + aoff[i] + soff);
#pragma unroll
        for (int j = 0; j < 2; j++)
            wR[j] = *reinterpret_cast<const float4*>(fN + s * 2048 + (tid + j * 256) * 4);
    };
    auto STS = [&](int buf) {
        float* A = sA0 + buf * ABUF;
        float* W = sW0 + buf * WBUF;
        // A: in-register transpose, 4 STS.128 (k-rows kq..kq+3)
        const float av[4][4] = {
            {aR[0].x, aR[1].x, aR[2].x, aR[3].x},
            {aR[0].y, aR[1].y, aR[2].y, aR[3].y},
            {aR[0].z, aR[1].z, aR[2].z, aR[3].z},
            {aR[0].w, aR[1].w, aR[2].w, aR[3].w}};
#pragma unroll
        for (int e = 0; e < 4; e++) {
            const int k = kslot * 4 + e;
            const int col = (mg * 4 + k * 4) & 127;
            *reinterpret_cast<float4*>(A + k * 128 + col) =
                make_float4(av[e][0], av[e][1], av[e][2], av[e][3]);
        }
        // W: duplicate pairs
#pragma unroll
        for (int j = 0; j < 2; j++) {
            const int f4 = tid + j * 256;
            const int kl = f4 >> 4;
            const int c4 = (f4 & 15) * 4;
            const float wv[4] = {wR[j].x, wR[j].y, wR[j].z, wR[j].w};
#pragma unroll
            for (int e = 0; e < 4; e++) {
                const int c = c4 + e;
                *reinterpret_cast<float2*>(
                    W + kl * 128 + ((c & 7) >> 1) * 32 + (c >> 3) * 4 + (c & 1) * 2) =
                    make_float2(wv[e], wv[e]);
            }
        }
    };

    ull acc[2][8];
#pragma unroll
    for (int p = 0; p < 2; p++)
#pragma unroll
        for (int j = 0; j < 8; j++) acc[p][j] = 0ull;

    const int pg = mg;         // m-rows 4*pg..4*pg+3
    const int cg = tid & 7;    // channels 8*cg..8*cg+7

    LDG(0);
    STS(0);
    __syncthreads();

#pragma unroll 1
    for (int s = 0; s < 8; s++) {
        if (s < 7) LDG(s + 1);
        const float* A = sA0 + (s & 1) * ABUF;
        const float* W = sW0 + (s & 1) * WBUF;
#pragma unroll 4
        for (int k = 0; k < 32; k++) {
            const ulonglong2 a =
                *reinterpret_cast<const ulonglong2*>(A + k * 128 + ((pg * 4 + k * 4) & 127));
            const float* wrow = W + k * 128 + cg * 4;
            const ulonglong2 w0 = *reinterpret_cast<const ulonglong2*>(wrow);
            const ulonglong2 w1 = *reinterpret_cast<const ulonglong2*>(wrow + 32);
            const ulonglong2 w2 = *reinterpret_cast<const ulonglong2*>(wrow + 64);
            const ulonglong2 w3 = *reinterpret_cast<const ulonglong2*>(wrow + 96);
            fma2(acc[0][0], a.x, w0.x); fma2(acc[0][1], a.x, w0.y);
            fma2(acc[0][2], a.x, w1.x); fma2(acc[0][3], a.x, w1.y);
            fma2(acc[0][4], a.x, w2.x); fma2(acc[0][5], a.x, w2.y);
            fma2(acc[0][6], a.x, w3.x); fma2(acc[0][7], a.x, w3.y);
            fma2(acc[1][0], a.y, w0.x); fma2(acc[1][1], a.y, w0.y);
            fma2(acc[1][2], a.y, w1.x); fma2(acc[1][3], a.y, w1.y);
            fma2(acc[1][4], a.y, w2.x); fma2(acc[1][5], a.y, w2.y);
            fma2(acc[1][6], a.y, w3.x); fma2(acc[1][7], a.y, w3.y);
        }
        if (s < 7) STS((s + 1) & 1);
        __syncthreads();
    }

    // Epilogue. acc[p][j]: lanes = m rows (4pg+2p, 4pg+2p+1), channel 8cg+j.
    const float4 b0 = *reinterpret_cast<const float4*>(bN + cg * 8);
    const float4 b1 = *reinterpret_cast<const float4*>(bN + cg * 8 + 4);
    const float bv[8] = {b0.x, b0.y, b0.z, b0.w, b1.x, b1.y, b1.z, b1.w};
#pragma unroll
    for (int p = 0; p < 2; p++) {
        float2 uj[8];
#pragma unroll
        for (int j = 0; j < 8; j++) uj[j] = unpack2(acc[p][j]);
        const int me = m0 + pg * 4 + 2 * p;
        float* ope = out + ((size_t)node * M + me) * C + cg * 8;
        float* opo = ope + C;
        float4 e0 = make_float4(fmaxf(uj[0].x + bv[0], 0.f), fmaxf(uj[1].x + bv[1], 0.f),
                                fmaxf(uj[2].x + bv[2], 0.f), fmaxf(uj[3].x + bv[3], 0.f));
        float4 e1 = make_float4(fmaxf(uj[4].x + bv[4], 0.f), fmaxf(uj[5].x + bv[5], 0.f),
                                fmaxf(uj[6].x + bv[6], 0.f), fmaxf(uj[7].x + bv[7], 0.f));
        float4 o0 = make_float4(fmaxf(uj[0].y + bv[0], 0.f), fmaxf(uj[1].y + bv[1], 0.f),
                                fmaxf(uj[2].y + bv[2], 0.f), fmaxf(uj[3].y + bv[3], 0.f));
        float4 o1 = make_float4(fmaxf(uj[4].y + bv[4], 0.f), fmaxf(uj[5].y + bv[5], 0.f),
                                fmaxf(uj[6].y + bv[6], 0.f), fmaxf(uj[7].y + bv[7], 0.f));
        *reinterpret_cast<float4*>(ope) = e0;
        *reinterpret_cast<float4*>(ope + 4) = e1;
        *reinterpret_cast<float4*>(opo) = o0;
        *reinterpret_cast<float4*>(opo + 4) = o1;
    }
}

// ---------------------------------------------------------------------------
// Decode: per node out[u,v,b,r,k] = sum_c feats[u,v,b,c]*Wd[u,v,r,c,k].
// ---------------------------------------------------------------------------
__global__ void __launch_bounds__(256) decode(
    const float* __restrict__ feats, const float* __restrict__ Wd,
    float* __restrict__ out) {
    extern __shared__ float dsm[];
    float* sF = dsm;
    float* sWd = dsm + 8192;
    const int tid = threadIdx.x;
    const int node = blockIdx.x, u = node >> 3, v = node & 7;
    const float* fN = feats + (size_t)node * 8192;
    const float* wN = Wd + (size_t)node * 8192;
#pragma unroll
    for (int j = 0; j < 8; j++) {
        const int f4 = tid + j * 256;
        reinterpret_cast<float4*>(sF)[f4] = reinterpret_cast<const float4*>(fN)[f4];
        reinterpret_cast<float4*>(sWd)[f4] = reinterpret_cast<const float4*>(wN)[f4];
    }
    __syncthreads();
    const int bg = tid >> 4, ng = tid & 15, r = ng >> 3, kk0 = (ng & 7) * 8;
    float acc[8][8];
#pragma unroll
    for (int i = 0; i < 8; i++)
#pragma unroll
        for (int j = 0; j < 8; j++) acc[i][j] = 0.0f;
#pragma unroll 4
    for (int k = 0; k < 64; k++) {
        const float4 w0 = *reinterpret_cast<const float4*>(sWd + r * 4096 + k * 64 + kk0);
        const float4 w1 = *reinterpret_cast<const float4*>(sWd + r * 4096 + k * 64 + kk0 + 4);
        const float wv[8] = {w0.x, w0.y, w0.z, w0.w, w1.x, w1.y, w1.z, w1.w};
#pragma unroll
        for (int i = 0; i < 8; i++) {
            const float a = sF[(bg * 8 + i) * 64 + k];
#pragma unroll
            for (int j = 0; j < 8; j++) acc[i][j] += a * wv[j];
        }
    }
    const int ou = ng & 7;
#pragma unroll
    for (int i = 0; i < 8; i++) {
        const int b = bg * 8 + i;
#pragma unroll
        for (int j = 0; j < 8; j++)
            out[(((size_t)b * 64 + u * 8 + ou) * 64 + (v * 8 + j)) * 2 + r] = acc[i][j];
    }
}

// ---------------------------------------------------------------------------
extern "C" void kernel_launch(void* const* d_in, const int* in_sizes, int n_in,
                              void* d_out, int out_size) {
    const float* in_data = (const float*)d_in[0];
    const float* in_filter = (const float*)d_in[1];
    const float* in_bias = (const float*)d_in[2];
    const float* f[6];
    const float* bb[6];
    for (int l = 0; l < 6; l++) {
        f[l] = (const float*)d_in[3 + 2 * l];
        bb[l] = (const float*)d_in[4 + 2 * l];
    }
    const float* Wd = (const float*)d_in[15];
    float* out = (float*)d_out;

    float *A, *B;
    cudaGetSymbolAddress((void**)&A, g_bufA);
    cudaGetSymbolAddress((void**)&B, g_bufB);

    constexpr int SMB = 2 * (32 * 128 + 32 * 128) * 4;  // 65,536 B
    cudaFuncSetAttribute(node_conv<2, 1, 32>, cudaFuncAttributeMaxDynamicSharedMemorySize, SMB);
    cudaFuncSetAttribute(node_conv<4, 2, 16>, cudaFuncAttributeMaxDynamicSharedMemorySize, SMB);
    cudaFuncSetAttribute(node_conv<8, 4, 8>, cudaFuncAttributeMaxDynamicSharedMemorySize, SMB);
    cudaFuncSetAttribute(node_conv<8, 8, 4>, cudaFuncAttributeMaxDynamicSharedMemorySize, SMB);
    cudaFuncSetAttribute(node_conv<8, 8, 2>, cudaFuncAttributeMaxDynamicSharedMemorySize, SMB);
    cudaFuncSetAttribute(node_conv<8, 8, 1>, cudaFuncAttributeMaxDynamicSharedMemorySize, SMB);
    cudaFuncSetAttribute(decode, cudaFuncAttributeMaxDynamicSharedMemorySize, 65536);

    first_conv<<<32768, 256>>>(in_data, in_filter, in_bias, A);
    node_conv<2, 1, 32><<<dim3(1024, 4), 256, SMB>>>(A, f[0], bb[0], B);
    node_conv<4, 2, 16><<<dim3(256, 16), 256, SMB>>>(B, f[1], bb[1], A);
    node_conv<8, 4, 8><<<dim3(64, 64), 256, SMB>>>(A, f[2], bb[2], B);
    node_conv<8, 8, 4><<<dim3(16, 64), 256, SMB>>>(B, f[3], bb[3], A);
    node_conv<8, 8, 2><<<dim3(4, 64), 256, SMB>>>(A, f[4], bb[4], B);
    node_conv<8, 8, 1><<<dim3(1, 64), 256, SMB>>>(B, f[5], bb[5], A);
    decode<<<64, 256, 65536>>>(A, Wd, out);
}

// round 9
// speedup vs baseline: 1.1149x; 1.1149x over previous
#include <cuda_runtime.h>
#include <cstdint>

using ull = unsigned long long;

__device__ __forceinline__ float2 unpack2(ull v) {
    float2 f; asm("mov.b64 {%0,%1},%2;" : "=f"(f.x), "=f"(f.y) : "l"(v)); return f;
}
__device__ __forceinline__ void fma2(ull& d, ull a, ull b) {
    asm("fma.rn.f32x2 %0,%1,%2,%0;" : "+l"(d) : "l"(a), "l"(b));
}

// Ping-pong activation buffers; __device__ globals are the sanctioned scratch.
__device__ float g_bufA[33554432];
__device__ float g_bufB[33554432];

// ---------------------------------------------------------------------------
// First conv: non-overlapping 4x4 patches -> 64 ch + ReLU.
// ---------------------------------------------------------------------------
__global__ void __launch_bounds__(256) first_conv(
    const float* __restrict__ in, const float* __restrict__ fw,
    const float* __restrict__ bias, float* __restrict__ out) {
    __shared__ float sIn[16 * 17];
    __shared__ float sW[1024];
    __shared__ float sB[64];
    const int tid = threadIdx.x;
    for (int j = tid; j < 1024; j += 256) sW[j] = fw[j];
    if (tid < 64) sB[tid] = bias[tid];
    const int P0 = blockIdx.x * 16;
    if (tid < 64) {
        const int pix = tid >> 2, p = tid & 3;
        const int P = P0 + pix, b = P >> 12, x = (P >> 6) & 63, y = P & 63;
        float4 v = *reinterpret_cast<const float4*>(
            in + ((size_t)(b * 256 + 4 * x + p)) * 256 + 4 * y);
        sIn[pix * 17 + p * 4 + 0] = v.x;
        sIn[pix * 17 + p * 4 + 1] = v.y;
        sIn[pix * 17 + p * 4 + 2] = v.z;
        sIn[pix * 17 + p * 4 + 3] = v.w;
    }
    __syncthreads();
    const int c = tid & 63, pq = tid >> 6;
    float acc[4] = {sB[c], sB[c], sB[c], sB[c]};
#pragma unroll
    for (int i = 0; i < 16; i++) {
        const float w = sW[i * 64 + c];
#pragma unroll
        for (int j = 0; j < 4; j++) acc[j] += sIn[(pq * 4 + j) * 17 + i] * w;
    }
#pragma unroll
    for (int j = 0; j < 4; j++)
        out[(size_t)(P0 + pq * 4 + j) * 64 + c] = fmaxf(acc[j], 0.0f);
}

// ---------------------------------------------------------------------------
// Node conv.  Per node GEMM: M=B*H*H, K=256 (8 stages of 32), N=64.
// MT=NT m-rows per block, 8m x 8n microtile, 2 blocks/SM (regs capped 128).
// sA: k-major [k][MT] with 16B-granule XOR swizzle col4 = (m>>2)^(k&7):
//   reads 1-phase, transpose-stores 4-phase, 16B alignment preserved.
// sW: {w,w} dup pairs (R8 layout, measured 1-phase reads).
// Inner loop per k: 2 A-LDS.128 (direct FFMA2 pairs) + 4 W-LDS.128 +
// 32 FFMA2 — zero packs.  Double-buffered, one barrier per stage.
// ---------------------------------------------------------------------------
template <int NU, int NP, int HO, int NT>
__global__ void __launch_bounds__(NT, 2) node_conv(
    const float* __restrict__ in, const float* __restrict__ fw,
    const float* __restrict__ bias, float* __restrict__ out) {
    constexpr int Bn = 128, C = 64, HI = 2 * HO, WI = 2 * HO, WO = HO;
    constexpr int M = Bn * HO * WO;
    constexpr int MT = NT;
    constexpr int ABUF = 32 * MT;
    constexpr int WBUF = 32 * 128;
    constexpr int WJ = 512 / NT;

    extern __shared__ float smem[];
    float* sA0 = smem;             // 2 * ABUF
    float* sW0 = smem + 2 * ABUF;  // 2 * WBUF

    const int tid = threadIdx.x;
    const int node = blockIdx.y;
    const int u = node / NU, v = node % NU;
    const int pu = (NP < NU) ? (u >> 1) : u;
    const int pv = (NP < NU) ? (v >> 1) : v;
    const float* inN = in + (size_t)(pu * NP + pv) * Bn * HI * WI * C;
    const float* fN = fw + (size_t)node * 4 * C * C;
    const float* bN = bias + (size_t)node * C;
    const int m0 = blockIdx.x * MT;

    const int kslot = tid & 7;  // owns k = 4*kslot..+3
    const int mgr = tid >> 3;   // owns m-rows 8*mgr..8*mgr+7 (= compute pg)

    unsigned aoff[8];
#pragma unroll
    for (int i = 0; i < 8; i++) {
        const int m = m0 + mgr * 8 + i;
        const int b = m / (HO * WO);
        const int hw = m - b * HO * WO;
        const int h = hw / WO, w = hw - h * WO;
        aoff[i] = (unsigned)((((b * HI + 2 * h) * WI + 2 * w) * C) + kslot * 4);
    }

    float4 aR[8], wR[WJ];
    auto LDG = [&](int s) {
        const int x = s >> 2, y = (s >> 1) & 1, cb = (s & 1) * 32;
        const unsigned soff = (unsigned)((x * WI + y) * C + cb);
#pragma unroll
        for (int i = 0; i < 8; i++)
            aR[i] = *reinterpret_cast<const float4*>(inN + aoff[i] + soff);
#pragma unroll
        for (int j = 0; j < WJ; j++)
            wR[j] = *reinterpret_cast<const float4*>(fN + s * 2048 + (tid + j * NT) * 4);
    };
    auto STS = [&](int buf) {
        float* A = sA0 + buf * ABUF;
        float* W = sW0 + buf * WBUF;
        // A: in-register transpose; per k-row two STS.128 at XOR-swizzled cols
#pragma unroll
        for (int e = 0; e < 4; e++) {
            const int k = kslot * 4 + e;
            const float* a0 = &aR[0].x;  // aR is contiguous float4[8]
            float v0[4], v1[4];
#pragma unroll
            for (int i = 0; i < 4; i++) v0[i] = (&aR[i].x)[e];
#pragma unroll
            for (int i = 0; i < 4; i++) v1[i] = (&aR[4 + i].x)[e];
            const int c40 = (mgr * 2) ^ (k & 7);
            const int c41 = (mgr * 2 + 1) ^ (k & 7);
            *reinterpret_cast<float4*>(A + k * MT + c40 * 4) =
                make_float4(v0[0], v0[1], v0[2], v0[3]);
            *reinterpret_cast<float4*>(A + k * MT + c41 * 4) =
                make_float4(v1[0], v1[1], v1[2], v1[3]);
            (void)a0;
        }
        // W: duplicate pairs (R8 layout)
#pragma unroll
        for (int j = 0; j < WJ; j++) {
            const int f4 = tid + j * NT;
            const int kl = f4 >> 4;
            const int c4 = (f4 & 15) * 4;
            const float wv[4] = {wR[j].x, wR[j].y, wR[j].z, wR[j].w};
#pragma unroll
            for (int e = 0; e < 4; e++) {
                const int c = c4 + e;
                *reinterpret_cast<float2*>(
                    W + kl * 128 + ((c & 7) >> 1) * 32 + (c >> 3) * 4 + (c & 1) * 2) =
                    make_float2(wv[e], wv[e]);
            }
        }
    };

    ull acc[4][8];
#pragma unroll
    for (int p = 0; p < 4; p++)
#pragma unroll
        for (int j = 0; j < 8; j++) acc[p][j] = 0ull;

    const int pg = mgr;      // m-rows 8*pg..8*pg+7
    const int cg = tid & 7;  // channels 8*cg..8*cg+7

    LDG(0);
    STS(0);
    __syncthreads();

#pragma unroll 1
    for (int s = 0; s < 8; s++) {
        if (s < 7) LDG(s + 1);
        const float* A = sA0 + (s & 1) * ABUF;
        const float* W = sW0 + (s & 1) * WBUF;
#pragma unroll 4
        for (int k = 0; k < 32; k++) {
            const ulonglong2 a01 = *reinterpret_cast<const ulonglong2*>(
                A + k * MT + ((pg * 2) ^ (k & 7)) * 4);
            const ulonglong2 a23 = *reinterpret_cast<const ulonglong2*>(
                A + k * MT + ((pg * 2 + 1) ^ (k & 7)) * 4);
            const float* wrow = W + k * 128 + cg * 4;
            const ulonglong2 w0 = *reinterpret_cast<const ulonglong2*>(wrow);
            const ulonglong2 w1 = *reinterpret_cast<const ulonglong2*>(wrow + 32);
            const ulonglong2 w2 = *reinterpret_cast<const ulonglong2*>(wrow + 64);
            const ulonglong2 w3 = *reinterpret_cast<const ulonglong2*>(wrow + 96);
            const ull a[4] = {a01.x, a01.y, a23.x, a23.y};
#pragma unroll
            for (int p = 0; p < 4; p++) {
                fma2(acc[p][0], a[p], w0.x);
                fma2(acc[p][1], a[p], w0.y);
                fma2(acc[p][2], a[p], w1.x);
                fma2(acc[p][3], a[p], w1.y);
                fma2(acc[p][4], a[p], w2.x);
                fma2(acc[p][5], a[p], w2.y);
                fma2(acc[p][6], a[p], w3.x);
                fma2(acc[p][7], a[p], w3.y);
            }
        }
        if (s < 7) STS((s + 1) & 1);
        __syncthreads();
    }

    // Epilogue. acc[p][j]: lanes = m rows (8pg+2p, 8pg+2p+1), channel 8cg+j.
    const float4 b0 = *reinterpret_cast<const float4*>(bN + cg * 8);
    const float4 b1 = *reinterpret_cast<const float4*>(bN + cg * 8 + 4);
    const float bv[8] = {b0.x, b0.y, b0.z, b0.w, b1.x, b1.y, b1.z, b1.w};
#pragma unroll
    for (int p = 0; p < 4; p++) {
        float2 uj[8];
#pragma unroll
        for (int j = 0; j < 8; j++) uj[j] = unpack2(acc[p][j]);
        const int me = m0 + pg * 8 + 2 * p;
        float* ope = out + ((size_t)node * M + me) * C + cg * 8;
        float* opo = ope + C;
        float4 e0 = make_float4(fmaxf(uj[0].x + bv[0], 0.f), fmaxf(uj[1].x + bv[1], 0.f),
                                fmaxf(uj[2].x + bv[2], 0.f), fmaxf(uj[3].x + bv[3], 0.f));
        float4 e1 = make_float4(fmaxf(uj[4].x + bv[4], 0.f), fmaxf(uj[5].x + bv[5], 0.f),
                                fmaxf(uj[6].x + bv[6], 0.f), fmaxf(uj[7].x + bv[7], 0.f));
        float4 o0 = make_float4(fmaxf(uj[0].y + bv[0], 0.f), fmaxf(uj[1].y + bv[1], 0.f),
                                fmaxf(uj[2].y + bv[2], 0.f), fmaxf(uj[3].y + bv[3], 0.f));
        float4 o1 = make_float4(fmaxf(uj[4].y + bv[4], 0.f), fmaxf(uj[5].y + bv[5], 0.f),
                                fmaxf(uj[6].y + bv[6], 0.f), fmaxf(uj[7].y + bv[7], 0.f));
        *reinterpret_cast<float4*>(ope) = e0;
        *reinterpret_cast<float4*>(ope + 4) = e1;
        *reinterpret_cast<float4*>(opo) = o0;
        *reinterpret_cast<float4*>(opo + 4) = o1;
    }
}

// ---------------------------------------------------------------------------
// Decode: per node out[u,v,b,r,k] = sum_c feats[u,v,b,c]*Wd[u,v,r,c,k].
// ---------------------------------------------------------------------------
__global__ void __launch_bounds__(256) decode(
    const float* __restrict__ feats, const float* __restrict__ Wd,
    float* __restrict__ out) {
    extern __shared__ float dsm[];
    float* sF = dsm;
    float* sWd = dsm + 8192;
    const int tid = threadIdx.x;
    const int node = blockIdx.x, u = node >> 3, v = node & 7;
    const float* fN = feats + (size_t)node * 8192;
    const float* wN = Wd + (size_t)node * 8192;
#pragma unroll
    for (int j = 0; j < 8; j++) {
        const int f4 = tid + j * 256;
        reinterpret_cast<float4*>(sF)[f4] = reinterpret_cast<const float4*>(fN)[f4];
        reinterpret_cast<float4*>(sWd)[f4] = reinterpret_cast<const float4*>(wN)[f4];
    }
    __syncthreads();
    const int bg = tid >> 4, ng = tid & 15, r = ng >> 3, kk0 = (ng & 7) * 8;
    float acc[8][8];
#pragma unroll
    for (int i = 0; i < 8; i++)
#pragma unroll
        for (int j = 0; j < 8; j++) acc[i][j] = 0.0f;
#pragma unroll 4
    for (int k = 0; k < 64; k++) {
        const float4 w0 = *reinterpret_cast<const float4*>(sWd + r * 4096 + k * 64 + kk0);
        const float4 w1 = *reinterpret_cast<const float4*>(sWd + r * 4096 + k * 64 + kk0 + 4);
        const float wv[8] = {w0.x, w0.y, w0.z, w0.w, w1.x, w1.y, w1.z, w1.w};
#pragma unroll
        for (int i = 0; i < 8; i++) {
            const float a = sF[(bg * 8 + i) * 64 + k];
#pragma unroll
            for (int j = 0; j < 8; j++) acc[i][j] += a * wv[j];
        }
    }
    const int ou = ng & 7;
#pragma unroll
    for (int i = 0; i < 8; i++) {
        const int b = bg * 8 + i;
#pragma unroll
        for (int j = 0; j < 8; j++)
            out[(((size_t)b * 64 + u * 8 + ou) * 64 + (v * 8 + j)) * 2 + r] = acc[i][j];
    }
}

// ---------------------------------------------------------------------------
extern "C" void kernel_launch(void* const* d_in, const int* in_sizes, int n_in,
                              void* d_out, int out_size) {
    const float* in_data = (const float*)d_in[0];
    const float* in_filter = (const float*)d_in[1];
    const float* in_bias = (const float*)d_in[2];
    const float* f[6];
    const float* bb[6];
    for (int l = 0; l < 6; l++) {
        f[l] = (const float*)d_in[3 + 2 * l];
        bb[l] = (const float*)d_in[4 + 2 * l];
    }
    const float* Wd = (const float*)d_in[15];
    float* out = (float*)d_out;

    float *A, *B;
    cudaGetSymbolAddress((void**)&A, g_bufA);
    cudaGetSymbolAddress((void**)&B, g_bufB);

    constexpr int SMB256 = 2 * (32 * 256 + 32 * 128) * 4;  // 98,304 B
    constexpr int SMB128 = 2 * (32 * 128 + 32 * 128) * 4;  // 65,536 B
    cudaFuncSetAttribute(node_conv<2, 1, 32, 256>, cudaFuncAttributeMaxDynamicSharedMemorySize, SMB256);
    cudaFuncSetAttribute(node_conv<4, 2, 16, 256>, cudaFuncAttributeMaxDynamicSharedMemorySize, SMB256);
    cudaFuncSetAttribute(node_conv<8, 4, 8, 256>, cudaFuncAttributeMaxDynamicSharedMemorySize, SMB256);
    cudaFuncSetAttribute(node_conv<8, 8, 4, 256>, cudaFuncAttributeMaxDynamicSharedMemorySize, SMB256);
    cudaFuncSetAttribute(node_conv<8, 8, 2, 256>, cudaFuncAttributeMaxDynamicSharedMemorySize, SMB256);
    cudaFuncSetAttribute(node_conv<8, 8, 1, 128>, cudaFuncAttributeMaxDynamicSharedMemorySize, SMB128);
    cudaFuncSetAttribute(decode, cudaFuncAttributeMaxDynamicSharedMemorySize, 65536);

    first_conv<<<32768, 256>>>(in_data, in_filter, in_bias, A);
    node_conv<2, 1, 32, 256><<<dim3(512, 4), 256, SMB256>>>(A, f[0], bb[0], B);
    node_conv<4, 2, 16, 256><<<dim3(128, 16), 256, SMB256>>>(B, f[1], bb[1], A);
    node_conv<8, 4, 8, 256><<<dim3(32, 64), 256, SMB256>>>(A, f[2], bb[2], B);
    node_conv<8, 8, 4, 256><<<dim3(8, 64), 256, SMB256>>>(B, f[3], bb[3], A);
    node_conv<8, 8, 2, 256><<<dim3(2, 64), 256, SMB256>>>(A, f[4], bb[4], B);
    node_conv<8, 8, 1, 128><<<dim3(1, 64), 128, SMB128>>>(B, f[5], bb[5], A);
    decode<<<64, 256, 65536>>>(A, Wd, out);
}

// round 10
// speedup vs baseline: 1.4691x; 1.3177x over previous
#include <cuda_runtime.h>
#include <cstdint>

using ull = unsigned long long;

__device__ __forceinline__ float2 unpack2(ull v) {
    float2 f; asm("mov.b64 {%0,%1},%2;" : "=f"(f.x), "=f"(f.y) : "l"(v)); return f;
}
__device__ __forceinline__ void fma2(ull& d, ull a, ull b) {
    asm("fma.rn.f32x2 %0,%1,%2,%0;" : "+l"(d) : "l"(a), "l"(b));
}

// Ping-pong activation buffers; __device__ globals are the sanctioned scratch.
__device__ float g_bufA[33554432];
__device__ float g_bufB[33554432];

// ---------------------------------------------------------------------------
// First conv: non-overlapping 4x4 patches -> 64 ch + ReLU.
// ---------------------------------------------------------------------------
__global__ void __launch_bounds__(256) first_conv(
    const float* __restrict__ in, const float* __restrict__ fw,
    const float* __restrict__ bias, float* __restrict__ out) {
    __shared__ float sIn[16 * 17];
    __shared__ float sW[1024];
    __shared__ float sB[64];
    const int tid = threadIdx.x;
    for (int j = tid; j < 1024; j += 256) sW[j] = fw[j];
    if (tid < 64) sB[tid] = bias[tid];
    const int P0 = blockIdx.x * 16;
    if (tid < 64) {
        const int pix = tid >> 2, p = tid & 3;
        const int P = P0 + pix, b = P >> 12, x = (P >> 6) & 63, y = P & 63;
        float4 v = *reinterpret_cast<const float4*>(
            in + ((size_t)(b * 256 + 4 * x + p)) * 256 + 4 * y);
        sIn[pix * 17 + p * 4 + 0] = v.x;
        sIn[pix * 17 + p * 4 + 1] = v.y;
        sIn[pix * 17 + p * 4 + 2] = v.z;
        sIn[pix * 17 + p * 4 + 3] = v.w;
    }
    __syncthreads();
    const int c = tid & 63, pq = tid >> 6;
    float acc[4] = {sB[c], sB[c], sB[c], sB[c]};
#pragma unroll
    for (int i = 0; i < 16; i++) {
        const float w = sW[i * 64 + c];
#pragma unroll
        for (int j = 0; j < 4; j++) acc[j] += sIn[(pq * 4 + j) * 17 + i] * w;
    }
#pragma unroll
    for (int j = 0; j < 4; j++)
        out[(size_t)(P0 + pq * 4 + j) * 64 + c] = fmaxf(acc[j], 0.0f);
}

// ---------------------------------------------------------------------------
// Node conv.  Per node GEMM: M=B*H*H, K=256 (8 stages of 32), N=64.
// NT=256, MT=128 m-rows/block, microtile 8m x 4n, 2 blocks/SM (regs ~75).
// sA: k-major [k][128], quartet XOR swizzle col4 = mg ^ kslot:
//   inner reads 1-phase, transpose-STS at the 4-phase floor.
// sW: {w,w} dup pairs in contiguous slots: slot = (c>>2) + 16*((c>>1)&1);
//   a warp's 16 slot reads span 256 contiguous bytes -> 2-phase LDS.128.
// Inner loop per k: 2 A-LDS + 2 W-LDS + 16 FFMA2, zero packs.
// Double-buffered, one barrier per stage.
// ---------------------------------------------------------------------------
template <int NU, int NP, int HO>
__global__ void __launch_bounds__(256, 2) node_conv(
    const float* __restrict__ in, const float* __restrict__ fw,
    const float* __restrict__ bias, float* __restrict__ out) {
    constexpr int Bn = 128, C = 64, HI = 2 * HO, WI = 2 * HO, WO = HO;
    constexpr int M = Bn * HO * WO;
    constexpr int MT = 128;
    constexpr int ABUF = 32 * 128;
    constexpr int WBUF = 32 * 128;

    extern __shared__ float smem[];
    float* sA0 = smem;             // 2 * ABUF
    float* sW0 = smem + 2 * ABUF;  // 2 * WBUF

    const int tid = threadIdx.x;
    const int node = blockIdx.y;
    const int u = node / NU, v = node % NU;
    const int pu = (NP < NU) ? (u >> 1) : u;
    const int pv = (NP < NU) ? (v >> 1) : v;
    const float* inN = in + (size_t)(pu * NP + pv) * Bn * HI * WI * C;
    const float* fN = fw + (size_t)node * 4 * C * C;
    const float* bN = bias + (size_t)node * C;
    const int m0 = blockIdx.x * MT;

    const int kslot = tid & 7;  // owns k = 4*kslot..+3 within a stage
    const int mg = tid >> 3;    // owns m-quartet 4*mg..4*mg+3 for staging

    unsigned aoff[4];
#pragma unroll
    for (int i = 0; i < 4; i++) {
        const int m = m0 + mg * 4 + i;
        const int b = m / (HO * WO);
        const int hw = m - b * HO * WO;
        const int h = hw / WO, w = hw - h * WO;
        aoff[i] = (unsigned)((((b * HI + 2 * h) * WI + 2 * w) * C) + kslot * 4);
    }

    float4 aR[4], wR[2];
    auto LDG = [&](int s) {
        const int x = s >> 2, y = (s >> 1) & 1, cb = (s & 1) * 32;
        const unsigned soff = (unsigned)((x * WI + y) * C + cb);
#pragma unroll
        for (int i = 0; i < 4; i++)
            aR[i] = *reinterpret_cast<const float4*>(inN + aoff[i] + soff);
#pragma unroll
        for (int j = 0; j < 2; j++)
            wR[j] = *reinterpret_cast<const float4*>(fN + s * 2048 + (tid + j * 256) * 4);
    };
    auto STS = [&](int buf) {
        float* A = sA0 + buf * ABUF;
        float* W = sW0 + buf * WBUF;
        // A: in-register transpose; one STS.128 per owned k-row.
        const int col4 = (mg ^ kslot) & 31;
#pragma unroll
        for (int e = 0; e < 4; e++) {
            const int k = kslot * 4 + e;
            *reinterpret_cast<float4*>(A + k * 128 + col4 * 4) = make_float4(
                (&aR[0].x)[e], (&aR[1].x)[e], (&aR[2].x)[e], (&aR[3].x)[e]);
        }
        // W: dup pairs into contiguous-slot layout.
#pragma unroll
        for (int j = 0; j < 2; j++) {
            const int f4 = tid + j * 256;
            const int kl = f4 >> 4;
            const int c4 = (f4 & 15) * 4;
            const float wv[4] = {wR[j].x, wR[j].y, wR[j].z, wR[j].w};
#pragma unroll
            for (int e = 0; e < 4; e++) {
                const int c = c4 + e;
                const int slot = (c >> 2) + 16 * ((c >> 1) & 1);
                *reinterpret_cast<float2*>(W + kl * 128 + slot * 4 + (c & 1) * 2) =
                    make_float2(wv[e], wv[e]);
            }
        }
    };

    ull acc[4][4];
#pragma unroll
    for (int p = 0; p < 4; p++)
#pragma unroll
        for (int j = 0; j < 4; j++) acc[p][j] = 0ull;

    const int pg = tid >> 4;   // 0..15 : m-rows 8*pg..8*pg+7
    const int cg = tid & 15;   // 0..15 : channels 4*cg..4*cg+3

    LDG(0);
    STS(0);
    __syncthreads();

#pragma unroll 1
    for (int s = 0; s < 8; s++) {
        if (s < 7) LDG(s + 1);
        const float* A = sA0 + (s & 1) * ABUF;
        const float* W = sW0 + (s & 1) * WBUF;
#pragma unroll 4
        for (int k = 0; k < 32; k++) {
            const int sw = k >> 2;
            const ulonglong2 a01 = *reinterpret_cast<const ulonglong2*>(
                A + k * 128 + (((2 * pg) ^ sw) & 31) * 4);
            const ulonglong2 a23 = *reinterpret_cast<const ulonglong2*>(
                A + k * 128 + (((2 * pg + 1) ^ sw) & 31) * 4);
            const ulonglong2 w01 =
                *reinterpret_cast<const ulonglong2*>(W + k * 128 + cg * 4);
            const ulonglong2 w23 =
                *reinterpret_cast<const ulonglong2*>(W + k * 128 + 64 + cg * 4);
            const ull a[4] = {a01.x, a01.y, a23.x, a23.y};
#pragma unroll
            for (int p = 0; p < 4; p++) {
                fma2(acc[p][0], a[p], w01.x);
                fma2(acc[p][1], a[p], w01.y);
                fma2(acc[p][2], a[p], w23.x);
                fma2(acc[p][3], a[p], w23.y);
            }
        }
        if (s < 7) STS((s + 1) & 1);
        __syncthreads();
    }

    // Epilogue. acc[p][j]: lanes = m rows (8pg+2p, 8pg+2p+1), channel 4cg+j.
    const float4 bb = *reinterpret_cast<const float4*>(bN + cg * 4);
    const float bv[4] = {bb.x, bb.y, bb.z, bb.w};
#pragma unroll
    for (int p = 0; p < 4; p++) {
        float2 uj[4];
#pragma unroll
        for (int j = 0; j < 4; j++) uj[j] = unpack2(acc[p][j]);
        const int me = m0 + pg * 8 + 2 * p;
        float* ope = out + ((size_t)node * M + me) * C + cg * 4;
        float* opo = ope + C;
        *reinterpret_cast<float4*>(ope) =
            make_float4(fmaxf(uj[0].x + bv[0], 0.f), fmaxf(uj[1].x + bv[1], 0.f),
                        fmaxf(uj[2].x + bv[2], 0.f), fmaxf(uj[3].x + bv[3], 0.f));
        *reinterpret_cast<float4*>(opo) =
            make_float4(fmaxf(uj[0].y + bv[0], 0.f), fmaxf(uj[1].y + bv[1], 0.f),
                        fmaxf(uj[2].y + bv[2], 0.f), fmaxf(uj[3].y + bv[3], 0.f));
    }
}

// ---------------------------------------------------------------------------
// Decode: per node out[u,v,b,r,k] = sum_c feats[u,v,b,c]*Wd[u,v,r,c,k].
// ---------------------------------------------------------------------------
__global__ void __launch_bounds__(256) decode(
    const float* __restrict__ feats, const float* __restrict__ Wd,
    float* __restrict__ out) {
    extern __shared__ float dsm[];
    float* sF = dsm;
    float* sWd = dsm + 8192;
    const int tid = threadIdx.x;
    const int node = blockIdx.x, u = node >> 3, v = node & 7;
    const float* fN = feats + (size_t)node * 8192;
    const float* wN = Wd + (size_t)node * 8192;
#pragma unroll
    for (int j = 0; j < 8; j++) {
        const int f4 = tid + j * 256;
        reinterpret_cast<float4*>(sF)[f4] = reinterpret_cast<const float4*>(fN)[f4];
        reinterpret_cast<float4*>(sWd)[f4] = reinterpret_cast<const float4*>(wN)[f4];
    }
    __syncthreads();
    const int bg = tid >> 4, ng = tid & 15, r = ng >> 3, kk0 = (ng & 7) * 8;
    float acc[8][8];
#pragma unroll
    for (int i = 0; i < 8; i++)
#pragma unroll
        for (int j = 0; j < 8; j++) acc[i][j] = 0.0f;
#pragma unroll 4
    for (int k = 0; k < 64; k++) {
        const float4 w0 = *reinterpret_cast<const float4*>(sWd + r * 4096 + k * 64 + kk0);
        const float4 w1 = *reinterpret_cast<const float4*>(sWd + r * 4096 + k * 64 + kk0 + 4);
        const float wv[8] = {w0.x, w0.y, w0.z, w0.w, w1.x, w1.y, w1.z, w1.w};
#pragma unroll
        for (int i = 0; i < 8; i++) {
            const float a = sF[(bg * 8 + i) * 64 + k];
#pragma unroll
            for (int j = 0; j < 8; j++) acc[i][j] += a * wv[j];
        }
    }
    const int ou = ng & 7;
#pragma unroll
    for (int i = 0; i < 8; i++) {
        const int b = bg * 8 + i;
#pragma unroll
        for (int j = 0; j < 8; j++)
            out[(((size_t)b * 64 + u * 8 + ou) * 64 + (v * 8 + j)) * 2 + r] = acc[i][j];
    }
}

// ---------------------------------------------------------------------------
extern "C" void kernel_launch(void* const* d_in, const int* in_sizes, int n_in,
                              void* d_out, int out_size) {
    const float* in_data = (const float*)d_in[0];
    const float* in_filter = (const float*)d_in[1];
    const float* in_bias = (const float*)d_in[2];
    const float* f[6];
    const float* bb[6];
    for (int l = 0; l < 6; l++) {
        f[l] = (const float*)d_in[3 + 2 * l];
        bb[l] = (const float*)d_in[4 + 2 * l];
    }
    const float* Wd = (const float*)d_in[15];
    float* out = (float*)d_out;

    float *A, *B;
    cudaGetSymbolAddress((void**)&A, g_bufA);
    cudaGetSymbolAddress((void**)&B, g_bufB);

    constexpr int SMB = 2 * (32 * 128 + 32 * 128) * 4;  // 65,536 B
    cudaFuncSetAttribute(node_conv<2, 1, 32>, cudaFuncAttributeMaxDynamicSharedMemorySize, SMB);
    cudaFuncSetAttribute(node_conv<4, 2, 16>, cudaFuncAttributeMaxDynamicSharedMemorySize, SMB);
    cudaFuncSetAttribute(node_conv<8, 4, 8>, cudaFuncAttributeMaxDynamicSharedMemorySize, SMB);
    cudaFuncSetAttribute(node_conv<8, 8, 4>, cudaFuncAttributeMaxDynamicSharedMemorySize, SMB);
    cudaFuncSetAttribute(node_conv<8, 8, 2>, cudaFuncAttributeMaxDynamicSharedMemorySize, SMB);
    cudaFuncSetAttribute(node_conv<8, 8, 1>, cudaFuncAttributeMaxDynamicSharedMemorySize, SMB);
    cudaFuncSetAttribute(decode, cudaFuncAttributeMaxDynamicSharedMemorySize, 65536);

    first_conv<<<32768, 256>>>(in_data, in_filter, in_bias, A);
    node_conv<2, 1, 32><<<dim3(1024, 4), 256, SMB>>>(A, f[0], bb[0], B);
    node_conv<4, 2, 16><<<dim3(256, 16), 256, SMB>>>(B, f[1], bb[1], A);
    node_conv<8, 4, 8><<<dim3(64, 64), 256, SMB>>>(A, f[2], bb[2], B);
    node_conv<8, 8, 4><<<dim3(16, 64), 256, SMB>>>(B, f[3], bb[3], A);
    node_conv<8, 8, 2><<<dim3(4, 64), 256, SMB>>>(A, f[4], bb[4], B);
    node_conv<8, 8, 1><<<dim3(1, 64), 256, SMB>>>(B, f[5], bb[5], A);
    decode<<<64, 256, 65536>>>(A, Wd, out);
}

// round 12
// speedup vs baseline: 1.5622x; 1.0634x over previous
#include <cuda_runtime.h>
#include <cstdint>

__device__ __forceinline__ uint32_t tf32u(float x) {
    uint32_t u; asm("cvt.rna.tf32.f32 %0, %1;" : "=r"(u) : "f"(x)); return u;
}
__device__ __forceinline__ float uaf(uint32_t u) { return __uint_as_float(u); }
__device__ __forceinline__ uint32_t fau(float f) { return __float_as_uint(f); }

#define MMA_TF32(c, a0, a1, a2, a3, b0, b1)                                   \
    asm volatile(                                                             \
        "mma.sync.aligned.m16n8k8.row.col.f32.tf32.tf32.f32 "                 \
        "{%0,%1,%2,%3},{%4,%5,%6,%7},{%8,%9},{%0,%1,%2,%3};"                  \
        : "+f"((c)[0]), "+f"((c)[1]), "+f"((c)[2]), "+f"((c)[3])              \
        : "r"(a0), "r"(a1), "r"(a2), "r"(a3), "r"(b0), "r"(b1))

// Static scratch (allocations forbidden).
__device__ float g_bufA[33554432];
__device__ float g_bufB[33554432];
__device__ float g_bufW[9043968];  // 276 nodes * 32768 floats (frag-packed hi|lo)

// ---------------------------------------------------------------------------
// First conv: non-overlapping 4x4 patches -> 64 ch + ReLU.
// ---------------------------------------------------------------------------
__global__ void __launch_bounds__(256) first_conv(
    const float* __restrict__ in, const float* __restrict__ fw,
    const float* __restrict__ bias, float* __restrict__ out) {
    __shared__ float sIn[16 * 17];
    __shared__ float sW[1024];
    __shared__ float sB[64];
    const int tid = threadIdx.x;
    for (int j = tid; j < 1024; j += 256) sW[j] = fw[j];
    if (tid < 64) sB[tid] = bias[tid];
    const int P0 = blockIdx.x * 16;
    if (tid < 64) {
        const int pix = tid >> 2, p = tid & 3;
        const int P = P0 + pix, b = P >> 12, x = (P >> 6) & 63, y = P & 63;
        float4 v = *reinterpret_cast<const float4*>(
            in + ((size_t)(b * 256 + 4 * x + p)) * 256 + 4 * y);
        sIn[pix * 17 + p * 4 + 0] = v.x;
        sIn[pix * 17 + p * 4 + 1] = v.y;
        sIn[pix * 17 + p * 4 + 2] = v.z;
        sIn[pix * 17 + p * 4 + 3] = v.w;
    }
    __syncthreads();
    const int c = tid & 63, pq = tid >> 6;
    float acc[4] = {sB[c], sB[c], sB[c], sB[c]};
#pragma unroll
    for (int i = 0; i < 16; i++) {
        const float w = sW[i * 64 + c];
#pragma unroll
        for (int j = 0; j < 4; j++) acc[j] += sIn[(pq * 4 + j) * 17 + i] * w;
    }
#pragma unroll
    for (int j = 0; j < 4; j++)
        out[(size_t)(P0 + pq * 4 + j) * 64 + c] = fmaxf(acc[j], 0.0f);
}

// ---------------------------------------------------------------------------
// W prep: per node, pack W into mma fragment order, tf32 hi/lo split.
// fw[node] is [k][n] row-major (k=(x*2+y)*64+ci, n=co).  Output per node
// (32768 floats): [plane2][sg32][ntp4][lane32][j4] where
// j = (b0,b1) of nt=2*ntp, then nt=2*ntp+1;  b0: k=sg*8+tig, n=nt*8+grp;
// b1: k+4.
// ---------------------------------------------------------------------------
__global__ void __launch_bounds__(256) prep_w(
    const float* __restrict__ f1, const float* __restrict__ f2,
    const float* __restrict__ f3, const float* __restrict__ f4,
    const float* __restrict__ f5, const float* __restrict__ f6,
    float* __restrict__ wt) {
    const int nb = blockIdx.x;  // 0..275
    const float* src;
    int local;
    if (nb < 4)        { src = f1; local = nb; }
    else if (nb < 20)  { src = f2; local = nb - 4; }
    else if (nb < 84)  { src = f3; local = nb - 20; }
    else if (nb < 148) { src = f4; local = nb - 84; }
    else if (nb < 212) { src = f5; local = nb - 148; }
    else               { src = f6; local = nb - 212; }
    src += (size_t)local * 16384;
    float* dst = wt + (size_t)nb * 32768;
    for (int o = threadIdx.x; o < 32768; o += 256) {
        const int p = o >> 14, rem = o & 16383;
        const int sg = rem >> 9, rem2 = rem & 511;
        const int ntp = rem2 >> 7, lane = (rem2 >> 2) & 31, j = o & 3;
        const int tig = lane & 3, grp = lane >> 2;
        const int nt = 2 * ntp + (j >> 1);
        const int k = sg * 8 + tig + (j & 1) * 4;
        const int n = nt * 8 + grp;
        const float w = src[k * 64 + n];
        const float hi = uaf(tf32u(w));
        dst[o] = p ? uaf(tf32u(w - hi)) : hi;
    }
}

// ---------------------------------------------------------------------------
// Tensor node conv via mma.sync m16n8k8 tf32, 3-split.
// Block 128m x 64n, warps 4m x 2n, warp tile 32x32 (2 m16 x 4 n8).
// A smem: [buf2][plane2][k32][136] with quartet-XOR swizzle
//   col4 = (m>>2) ^ ((k>>2)<<2): frag reads 1-phase, STS at 4-phase floor.
// B: fragment-packed in global (prep_w), 4 LDG.128/step, double-buffered.
// ---------------------------------------------------------------------------
template <int NU, int NP, int HO>
__global__ void __launch_bounds__(256, 2) node_mma(
    const float* __restrict__ in, const float* __restrict__ wfr,
    const float* __restrict__ bias, float* __restrict__ out) {
    constexpr int C = 64, HI = 2 * HO, WI = 2 * HO, WO = HO;
    constexpr int M = 128 * HO * WO;
    constexpr int PL = 4352;   // plane stride (32*136)
    constexpr int BUF = 8704;  // buffer stride (2 planes)

    extern __shared__ float smem[];
    const int tid = threadIdx.x;
    const int lane = tid & 31, warp = tid >> 5;
    const int wm = warp & 3, wn = warp >> 2;
    const int g = lane >> 2, tig = lane & 3;

    const int node = blockIdx.y;
    const int u = node / NU, v = node % NU;
    const int pu = (NP < NU) ? (u >> 1) : u;
    const int pv = (NP < NU) ? (v >> 1) : v;
    const float* inN = in + (size_t)(pu * NP + pv) * 128 * HI * WI * C;
    const float* bN = bias + (size_t)node * 64;
    const float4* wN4 = reinterpret_cast<const float4*>(wfr + (size_t)node * 32768);
    const int m0 = blockIdx.x * 128;

    // ---- staging geometry (thread owns 4m x 4k) ----
    const int mg = tid >> 3, kslot = tid & 7;
    unsigned aoff[4];
#pragma unroll
    for (int i = 0; i < 4; i++) {
        const int m = m0 + mg * 4 + i;
        const int b = m / (HO * WO);
        const int hw = m - b * HO * WO;
        const int h = hw / WO, w = hw - h * WO;
        aoff[i] = (unsigned)((((b * HI + 2 * h) * WI + 2 * w) * C) + kslot * 4);
    }
    float4 aR[4];
    auto LDG = [&](int s) {
        const int x = s >> 2, y = (s >> 1) & 1, cb = (s & 1) * 32;
        const unsigned soff = (unsigned)((x * WI + y) * C + cb);
#pragma unroll
        for (int i = 0; i < 4; i++)
            aR[i] = *reinterpret_cast<const float4*>(inN + aoff[i] + soff);
    };
    const int scol = ((mg ^ (kslot << 2)) & 31) * 4;
    auto STS = [&](int buf) {
        float* H = smem + buf * BUF;
        float* L = H + PL;
#pragma unroll
        for (int e = 0; e < 4; e++) {
            const int k = kslot * 4 + e;
            const float v0 = (&aR[0].x)[e], v1 = (&aR[1].x)[e];
            const float v2 = (&aR[2].x)[e], v3 = (&aR[3].x)[e];
            const float h0 = uaf(tf32u(v0)), h1 = uaf(tf32u(v1));
            const float h2 = uaf(tf32u(v2)), h3 = uaf(tf32u(v3));
            *reinterpret_cast<float4*>(H + k * 136 + scol) =
                make_float4(h0, h1, h2, h3);
            *reinterpret_cast<float4*>(L + k * 136 + scol) =
                make_float4(uaf(tf32u(v0 - h0)), uaf(tf32u(v1 - h1)),
                            uaf(tf32u(v2 - h2)), uaf(tf32u(v3 - h3)));
        }
    };

    // ---- B double buffer (fragment-packed LDG) ----
    float4 bB[2][4];
    auto loadB = [&](int sg) {
        const int base = sg * 128 + wn * 64 + lane;
        float4* d = bB[sg & 1];
        d[0] = wN4[base];
        d[1] = wN4[base + 32];
        d[2] = wN4[base + 4096];
        d[3] = wN4[base + 4096 + 32];
    };

    float c[2][4][4];
#pragma unroll
    for (int mt = 0; mt < 2; mt++)
#pragma unroll
        for (int nt = 0; nt < 4; nt++)
#pragma unroll
            for (int j = 0; j < 4; j++) c[mt][nt][j] = 0.0f;

    const int qm0 = wm * 8 + (g >> 2);  // m-quartet for mt=0 (mt=1: +4)
    const int r = g & 3;

    loadB(0);
    LDG(0);
    STS(0);
    __syncthreads();

#pragma unroll 1
    for (int s = 0; s < 8; s++) {
        if (s < 7) LDG(s + 1);
        const float* Ab = smem + (s & 1) * BUF;
#pragma unroll
        for (int s8 = 0; s8 < 4; s8++) {
            const int sg = s * 4 + s8;
            const float4* bc = bB[sg & 1];
            if (sg < 31) loadB(sg + 1);
            const int rowH = (s8 * 8 + tig) * 136;
            const int rowH2 = rowH + 544;  // +4*136
            const int Xa = s8 * 8, Xb = Xa + 4;
#pragma unroll
            for (int mt = 0; mt < 2; mt++) {
                const int q = qm0 + mt * 4;
                const int o0 = rowH + ((q ^ Xa) & 31) * 4 + r;
                const int o1 = rowH + (((q + 2) ^ Xa) & 31) * 4 + r;
                const int o2 = rowH2 + ((q ^ Xb) & 31) * 4 + r;
                const int o3 = rowH2 + (((q + 2) ^ Xb) & 31) * 4 + r;
                const uint32_t ah0 = fau(Ab[o0]), ah1 = fau(Ab[o1]);
                const uint32_t ah2 = fau(Ab[o2]), ah3 = fau(Ab[o3]);
                const uint32_t al0 = fau(Ab[PL + o0]), al1 = fau(Ab[PL + o1]);
                const uint32_t al2 = fau(Ab[PL + o2]), al3 = fau(Ab[PL + o3]);
#pragma unroll
                for (int nt = 0; nt < 4; nt++) {
                    const float4 h = bc[nt >> 1];
                    const float4 l = bc[2 + (nt >> 1)];
                    uint32_t b0h, b1h, b0l, b1l;
                    if (nt & 1) {
                        b0h = fau(h.z); b1h = fau(h.w);
                        b0l = fau(l.z); b1l = fau(l.w);
                    } else {
                        b0h = fau(h.x); b1h = fau(h.y);
                        b0l = fau(l.x); b1l = fau(l.y);
                    }
                    MMA_TF32(c[mt][nt], ah0, ah1, ah2, ah3, b0h, b1h);
                    MMA_TF32(c[mt][nt], al0, al1, al2, al3, b0h, b1h);
                    MMA_TF32(c[mt][nt], ah0, ah1, ah2, ah3, b0l, b1l);
                }
            }
        }
        if (s < 7) STS((s + 1) & 1);
        __syncthreads();
    }

    // ---- epilogue: bias + ReLU, float2 stores ----
#pragma unroll
    for (int mt = 0; mt < 2; mt++) {
#pragma unroll
        for (int nt = 0; nt < 4; nt++) {
            const int n0 = wn * 32 + nt * 8 + 2 * tig;
            const float2 bb = *reinterpret_cast<const float2*>(bN + n0);
            const int me = m0 + wm * 32 + mt * 16 + g;
            float* pe = out + ((size_t)node * M + me) * 64 + n0;
            float* po = pe + 8 * 64;
            *reinterpret_cast<float2*>(pe) = make_float2(
                fmaxf(c[mt][nt][0] + bb.x, 0.0f), fmaxf(c[mt][nt][1] + bb.y, 0.0f));
            *reinterpret_cast<float2*>(po) = make_float2(
                fmaxf(c[mt][nt][2] + bb.x, 0.0f), fmaxf(c[mt][nt][3] + bb.y, 0.0f));
        }
    }
}

// ---------------------------------------------------------------------------
// Decode: per node out[u,v,b,r,k] = sum_c feats[u,v,b,c]*Wd[u,v,r,c,k].
// ---------------------------------------------------------------------------
__global__ void __launch_bounds__(256) decode(
    const float* __restrict__ feats, const float* __restrict__ Wd,
    float* __restrict__ out) {
    extern __shared__ float dsm[];
    float* sF = dsm;
    float* sWd = dsm + 8192;
    const int tid = threadIdx.x;
    const int node = blockIdx.x, u = node >> 3, v = node & 7;
    const float* fN = feats + (size_t)node * 8192;
    const float* wN = Wd + (size_t)node * 8192;
#pragma unroll
    for (int j = 0; j < 8; j++) {
        const int f4 = tid + j * 256;
        reinterpret_cast<float4*>(sF)[f4] = reinterpret_cast<const float4*>(fN)[f4];
        reinterpret_cast<float4*>(sWd)[f4] = reinterpret_cast<const float4*>(wN)[f4];
    }
    __syncthreads();
    const int bg = tid >> 4, ng = tid & 15, rr = ng >> 3, kk0 = (ng & 7) * 8;
    float acc[8][8];
#pragma unroll
    for (int i = 0; i < 8; i++)
#pragma unroll
        for (int j = 0; j < 8; j++) acc[i][j] = 0.0f;
#pragma unroll 4
    for (int k = 0; k < 64; k++) {
        const float4 w0 = *reinterpret_cast<const float4*>(sWd + rr * 4096 + k * 64 + kk0);
        const float4 w1 = *reinterpret_cast<const float4*>(sWd + rr * 4096 + k * 64 + kk0 + 4);
        const float wv[8] = {w0.x, w0.y, w0.z, w0.w, w1.x, w1.y, w1.z, w1.w};
#pragma unroll
        for (int i = 0; i < 8; i++) {
            const float a = sF[(bg * 8 + i) * 64 + k];
#pragma unroll
            for (int j = 0; j < 8; j++) acc[i][j] += a * wv[j];
        }
    }
    const int ou = ng & 7;
#pragma unroll
    for (int i = 0; i < 8; i++) {
        const int b = bg * 8 + i;
#pragma unroll
        for (int j = 0; j < 8; j++)
            out[(((size_t)b * 64 + u * 8 + ou) * 64 + (v * 8 + j)) * 2 + rr] = acc[i][j];
    }
}

// ---------------------------------------------------------------------------
extern "C" void kernel_launch(void* const* d_in, const int* in_sizes, int n_in,
                              void* d_out, int out_size) {
    const float* in_data = (const float*)d_in[0];
    const float* in_filter = (const float*)d_in[1];
    const float* in_bias = (const float*)d_in[2];
    const float* f[6];
    const float* bb[6];
    for (int l = 0; l < 6; l++) {
        f[l] = (const float*)d_in[3 + 2 * l];
        bb[l] = (const float*)d_in[4 + 2 * l];
    }
    const float* Wd = (const float*)d_in[15];
    float* out = (float*)d_out;

    float *A, *B, *Wt;
    cudaGetSymbolAddress((void**)&A, g_bufA);
    cudaGetSymbolAddress((void**)&B, g_bufB);
    cudaGetSymbolAddress((void**)&Wt, g_bufW);

    constexpr int SMB = 2 * 8704 * 4;  // 69,632 B
    cudaFuncSetAttribute(node_mma<2, 1, 32>, cudaFuncAttributeMaxDynamicSharedMemorySize, SMB);
    cudaFuncSetAttribute(node_mma<4, 2, 16>, cudaFuncAttributeMaxDynamicSharedMemorySize, SMB);
    cudaFuncSetAttribute(node_mma<8, 4, 8>, cudaFuncAttributeMaxDynamicSharedMemorySize, SMB);
    cudaFuncSetAttribute(node_mma<8, 8, 4>, cudaFuncAttributeMaxDynamicSharedMemorySize, SMB);
    cudaFuncSetAttribute(node_mma<8, 8, 2>, cudaFuncAttributeMaxDynamicSharedMemorySize, SMB);
    cudaFuncSetAttribute(node_mma<8, 8, 1>, cudaFuncAttributeMaxDynamicSharedMemorySize, SMB);
    cudaFuncSetAttribute(decode, cudaFuncAttributeMaxDynamicSharedMemorySize, 65536);

    prep_w<<<276, 256>>>(f[0], f[1], f[2], f[3], f[4], f[5], Wt);
    first_conv<<<32768, 256>>>(in_data, in_filter, in_bias, A);
    node_mma<2, 1, 32><<<dim3(1024, 4), 256, SMB>>>(A, Wt + (size_t)0 * 32768, bb[0], B);
    node_mma<4, 2, 16><<<dim3(256, 16), 256, SMB>>>(B, Wt + (size_t)4 * 32768, bb[1], A);
    node_mma<8, 4, 8><<<dim3(64, 64), 256, SMB>>>(A, Wt + (size_t)20 * 32768, bb[2], B);
    node_mma<8, 8, 4><<<dim3(16, 64), 256, SMB>>>(B, Wt + (size_t)84 * 32768, bb[3], A);
    node_mma<8, 8, 2><<<dim3(4, 64), 256, SMB>>>(A, Wt + (size_t)148 * 32768, bb[4], B);
    node_mma<8, 8, 1><<<dim3(1, 64), 256, SMB>>>(B, Wt + (size_t)212 * 32768, bb[5], A);
    decode<<<64, 256, 65536>>>(A, Wd, out);
}

// round 13
// speedup vs baseline: 1.8307x; 1.1719x over previous
#include <cuda_runtime.h>
#include <cstdint>

__device__ __forceinline__ uint32_t tf32u(float x) {
    uint32_t u; asm("cvt.rna.tf32.f32 %0, %1;" : "=r"(u) : "f"(x)); return u;
}
__device__ __forceinline__ float uaf(uint32_t u) { return __uint_as_float(u); }
__device__ __forceinline__ uint32_t fau(float f) { return __float_as_uint(f); }

#define MMA_TF32(c, a0, a1, a2, a3, b0, b1)                                   \
    asm volatile(                                                             \
        "mma.sync.aligned.m16n8k8.row.col.f32.tf32.tf32.f32 "                 \
        "{%0,%1,%2,%3},{%4,%5,%6,%7},{%8,%9},{%0,%1,%2,%3};"                  \
        : "+f"((c)[0]), "+f"((c)[1]), "+f"((c)[2]), "+f"((c)[3])              \
        : "r"(a0), "r"(a1), "r"(a2), "r"(a3), "r"(b0), "r"(b1))

// Static scratch (allocations forbidden).
__device__ float g_bufA[33554432];
__device__ float g_bufB[33554432];
__device__ float g_bufW[9043968];  // 276 nodes * 32768 floats (frag-packed hi|lo)

// ---------------------------------------------------------------------------
// First conv: non-overlapping 4x4 patches -> 64 ch + ReLU.
// ---------------------------------------------------------------------------
__global__ void __launch_bounds__(256) first_conv(
    const float* __restrict__ in, const float* __restrict__ fw,
    const float* __restrict__ bias, float* __restrict__ out) {
    __shared__ float sIn[16 * 17];
    __shared__ float sW[1024];
    __shared__ float sB[64];
    const int tid = threadIdx.x;
    for (int j = tid; j < 1024; j += 256) sW[j] = fw[j];
    if (tid < 64) sB[tid] = bias[tid];
    const int P0 = blockIdx.x * 16;
    if (tid < 64) {
        const int pix = tid >> 2, p = tid & 3;
        const int P = P0 + pix, b = P >> 12, x = (P >> 6) & 63, y = P & 63;
        float4 v = *reinterpret_cast<const float4*>(
            in + ((size_t)(b * 256 + 4 * x + p)) * 256 + 4 * y);
        sIn[pix * 17 + p * 4 + 0] = v.x;
        sIn[pix * 17 + p * 4 + 1] = v.y;
        sIn[pix * 17 + p * 4 + 2] = v.z;
        sIn[pix * 17 + p * 4 + 3] = v.w;
    }
    __syncthreads();
    const int c = tid & 63, pq = tid >> 6;
    float acc[4] = {sB[c], sB[c], sB[c], sB[c]};
#pragma unroll
    for (int i = 0; i < 16; i++) {
        const float w = sW[i * 64 + c];
#pragma unroll
        for (int j = 0; j < 4; j++) acc[j] += sIn[(pq * 4 + j) * 17 + i] * w;
    }
#pragma unroll
    for (int j = 0; j < 4; j++)
        out[(size_t)(P0 + pq * 4 + j) * 64 + c] = fmaxf(acc[j], 0.0f);
}

// ---------------------------------------------------------------------------
// W prep: per node, pack W into mma fragment order, tf32 hi/lo split.
// ---------------------------------------------------------------------------
__global__ void __launch_bounds__(256) prep_w(
    const float* __restrict__ f1, const float* __restrict__ f2,
    const float* __restrict__ f3, const float* __restrict__ f4,
    const float* __restrict__ f5, const float* __restrict__ f6,
    float* __restrict__ wt) {
    const int nb = blockIdx.x;  // 0..275
    const float* src;
    int local;
    if (nb < 4)        { src = f1; local = nb; }
    else if (nb < 20)  { src = f2; local = nb - 4; }
    else if (nb < 84)  { src = f3; local = nb - 20; }
    else if (nb < 148) { src = f4; local = nb - 84; }
    else if (nb < 212) { src = f5; local = nb - 148; }
    else               { src = f6; local = nb - 212; }
    src += (size_t)local * 16384;
    float* dst = wt + (size_t)nb * 32768;
    for (int o = threadIdx.x; o < 32768; o += 256) {
        const int p = o >> 14, rem = o & 16383;
        const int sg = rem >> 9, rem2 = rem & 511;
        const int ntp = rem2 >> 7, lane = (rem2 >> 2) & 31, j = o & 3;
        const int tig = lane & 3, grp = lane >> 2;
        const int nt = 2 * ntp + (j >> 1);
        const int k = sg * 8 + tig + (j & 1) * 4;
        const int n = nt * 8 + grp;
        const float w = src[k * 64 + n];
        const float hi = uaf(tf32u(w));
        dst[o] = p ? uaf(tf32u(w - hi)) : hi;
    }
}

// ---------------------------------------------------------------------------
// Tensor node conv via mma.sync m16n8k8 tf32, 3-split.
// Block 128m x 64n, warps 4m x 2n, warp tile 32x32 (2 m16 x 4 n8).
// A smem is FRAGMENT-PACKED per k-stage: float4 idx =
//   plane*1024 + sg*256 + mtile*32 + swz(lane, sg),
//   swz(L,sg) = L ^ sg ^ (((L>>4)&1)<<2).
// Reader: one LDS.128 per (mt, plane) per k8-step — conflict-free.
// Writer: 32 scalar STS/thread/stage — bank-audited 1 phase each.
// B: fragment-packed in global (prep_w), 4 LDG.128/step, double-buffered.
// ---------------------------------------------------------------------------
template <int NU, int NP, int HO>
__global__ void __launch_bounds__(256, 2) node_mma(
    const float* __restrict__ in, const float* __restrict__ wfr,
    const float* __restrict__ bias, float* __restrict__ out) {
    constexpr int C = 64, HI = 2 * HO, WI = 2 * HO, WO = HO;
    constexpr int M = 128 * HO * WO;
    constexpr int BUF4 = 2048;  // float4s per stage buffer (2 planes x 1024)

    extern __shared__ float smem[];
    float4* s4 = reinterpret_cast<float4*>(smem);
    const int tid = threadIdx.x;
    const int lane = tid & 31, warp = tid >> 5;
    const int wm = warp & 3, wn = warp >> 2;
    const int g = lane >> 2, tig = lane & 3;

    const int node = blockIdx.y;
    const int u = node / NU, v = node % NU;
    const int pu = (NP < NU) ? (u >> 1) : u;
    const int pv = (NP < NU) ? (v >> 1) : v;
    const float* inN = in + (size_t)(pu * NP + pv) * 128 * HI * WI * C;
    const float* bN = bias + (size_t)node * 64;
    const float4* wN4 = reinterpret_cast<const float4*>(wfr + (size_t)node * 32768);
    const int m0 = blockIdx.x * 128;

    // ---- staging geometry (thread owns 4m x 4k) ----
    const int mg = tid >> 3, kslot = tid & 7;
    unsigned aoff[4];
#pragma unroll
    for (int i = 0; i < 4; i++) {
        const int m = m0 + mg * 4 + i;
        const int b = m / (HO * WO);
        const int hw = m - b * HO * WO;
        const int h = hw / WO, w = hw - h * WO;
        aoff[i] = (unsigned)((((b * HI + 2 * h) * WI + 2 * w) * C) + kslot * 4);
    }
    float4 aR[4];
    auto LDG = [&](int s) {
        const int x = s >> 2, y = (s >> 1) & 1, cb = (s & 1) * 32;
        const unsigned soff = (unsigned)((x * WI + y) * C + cb);
#pragma unroll
        for (int i = 0; i < 4; i++)
            aR[i] = *reinterpret_cast<const float4*>(inN + aoff[i] + soff);
    };

    // Writer constants: sgW/jW fixed per thread; lane' = 16(mg&1)+4i+e.
    const int sgW = kslot >> 1;
    const int jW = ((mg >> 1) & 1) + 2 * (kslot & 1);
    const int mtileW = mg >> 2;
    const int lpBase = 16 * (mg & 1);
    auto STS = [&](int buf) {
        float* base = smem + buf * BUF4 * 4;  // scalar view
#pragma unroll
        for (int i = 0; i < 4; i++) {
            const float vals[4] = {(&aR[i].x)[0], (&aR[i].x)[1],
                                   (&aR[i].x)[2], (&aR[i].x)[3]};
#pragma unroll
            for (int e = 0; e < 4; e++) {
                const int lp = lpBase + 4 * i + e;
                const int lsw = lp ^ sgW ^ (((lp >> 4) & 1) << 2);
                const int f4i = sgW * 256 + mtileW * 32 + lsw;
                const float x = vals[e];
                const float h = uaf(tf32u(x));
                base[f4i * 4 + jW] = h;
                base[(1024 + f4i) * 4 + jW] = uaf(tf32u(x - h));
            }
        }
    };

    // ---- B double buffer (fragment-packed LDG) ----
    float4 bB[2][4];
    auto loadB = [&](int sg) {
        const int base = sg * 128 + wn * 64 + lane;
        float4* d = bB[sg & 1];
        d[0] = wN4[base];
        d[1] = wN4[base + 32];
        d[2] = wN4[base + 4096];
        d[3] = wN4[base + 4096 + 32];
    };

    float c[2][4][4];
#pragma unroll
    for (int mt = 0; mt < 2; mt++)
#pragma unroll
        for (int nt = 0; nt < 4; nt++)
#pragma unroll
            for (int j = 0; j < 4; j++) c[mt][nt][j] = 0.0f;

    const int Lc = lane ^ (((lane >> 4) & 1) << 2);

    loadB(0);
    LDG(0);
    STS(0);
    __syncthreads();

#pragma unroll 1
    for (int s = 0; s < 8; s++) {
        if (s < 7) LDG(s + 1);
        const float4* Ab = s4 + (s & 1) * BUF4;
#pragma unroll
        for (int s8 = 0; s8 < 4; s8++) {
            const int sg = s * 4 + s8;
            const float4* bc = bB[sg & 1];
            if (sg < 31) loadB(sg + 1);
            const int fb = s8 * 256 + (Lc ^ s8);
#pragma unroll
            for (int mt = 0; mt < 2; mt++) {
                const float4 h4 = Ab[fb + (wm * 2 + mt) * 32];
                const float4 l4 = Ab[1024 + fb + (wm * 2 + mt) * 32];
                const uint32_t ah0 = fau(h4.x), ah1 = fau(h4.y);
                const uint32_t ah2 = fau(h4.z), ah3 = fau(h4.w);
                const uint32_t al0 = fau(l4.x), al1 = fau(l4.y);
                const uint32_t al2 = fau(l4.z), al3 = fau(l4.w);
#pragma unroll
                for (int nt = 0; nt < 4; nt++) {
                    const float4 h = bc[nt >> 1];
                    const float4 l = bc[2 + (nt >> 1)];
                    uint32_t b0h, b1h, b0l, b1l;
                    if (nt & 1) {
                        b0h = fau(h.z); b1h = fau(h.w);
                        b0l = fau(l.z); b1l = fau(l.w);
                    } else {
                        b0h = fau(h.x); b1h = fau(h.y);
                        b0l = fau(l.x); b1l = fau(l.y);
                    }
                    MMA_TF32(c[mt][nt], ah0, ah1, ah2, ah3, b0h, b1h);
                    MMA_TF32(c[mt][nt], al0, al1, al2, al3, b0h, b1h);
                    MMA_TF32(c[mt][nt], ah0, ah1, ah2, ah3, b0l, b1l);
                }
            }
        }
        if (s < 7) STS((s + 1) & 1);
        __syncthreads();
    }

    // ---- epilogue: bias + ReLU, float2 stores ----
#pragma unroll
    for (int mt = 0; mt < 2; mt++) {
#pragma unroll
        for (int nt = 0; nt < 4; nt++) {
            const int n0 = wn * 32 + nt * 8 + 2 * tig;
            const float2 bb = *reinterpret_cast<const float2*>(bN + n0);
            const int me = m0 + wm * 32 + mt * 16 + g;
            float* pe = out + ((size_t)node * M + me) * 64 + n0;
            float* po = pe + 8 * 64;
            *reinterpret_cast<float2*>(pe) = make_float2(
                fmaxf(c[mt][nt][0] + bb.x, 0.0f), fmaxf(c[mt][nt][1] + bb.y, 0.0f));
            *reinterpret_cast<float2*>(po) = make_float2(
                fmaxf(c[mt][nt][2] + bb.x, 0.0f), fmaxf(c[mt][nt][3] + bb.y, 0.0f));
        }
    }
}

// ---------------------------------------------------------------------------
// Decode: per node out[u,v,b,r,k] = sum_c feats[u,v,b,c]*Wd[u,v,r,c,k].
// ---------------------------------------------------------------------------
__global__ void __launch_bounds__(256) decode(
    const float* __restrict__ feats, const float* __restrict__ Wd,
    float* __restrict__ out) {
    extern __shared__ float dsm[];
    float* sF = dsm;
    float* sWd = dsm + 8192;
    const int tid = threadIdx.x;
    const int node = blockIdx.x, u = node >> 3, v = node & 7;
    const float* fN = feats + (size_t)node * 8192;
    const float* wN = Wd + (size_t)node * 8192;
#pragma unroll
    for (int j = 0; j < 8; j++) {
        const int f4 = tid + j * 256;
        reinterpret_cast<float4*>(sF)[f4] = reinterpret_cast<const float4*>(fN)[f4];
        reinterpret_cast<float4*>(sWd)[f4] = reinterpret_cast<const float4*>(wN)[f4];
    }
    __syncthreads();
    const int bg = tid >> 4, ng = tid & 15, rr = ng >> 3, kk0 = (ng & 7) * 8;
    float acc[8][8];
#pragma unroll
    for (int i = 0; i < 8; i++)
#pragma unroll
        for (int j = 0; j < 8; j++) acc[i][j] = 0.0f;
#pragma unroll 4
    for (int k = 0; k < 64; k++) {
        const float4 w0 = *reinterpret_cast<const float4*>(sWd + rr * 4096 + k * 64 + kk0);
        const float4 w1 = *reinterpret_cast<const float4*>(sWd + rr * 4096 + k * 64 + kk0 + 4);
        const float wv[8] = {w0.x, w0.y, w0.z, w0.w, w1.x, w1.y, w1.z, w1.w};
#pragma unroll
        for (int i = 0; i < 8; i++) {
            const float a = sF[(bg * 8 + i) * 64 + k];
#pragma unroll
            for (int j = 0; j < 8; j++) acc[i][j] += a * wv[j];
        }
    }
    const int ou = ng & 7;
#pragma unroll
    for (int i = 0; i < 8; i++) {
        const int b = bg * 8 + i;
#pragma unroll
        for (int j = 0; j < 8; j++)
            out[(((size_t)b * 64 + u * 8 + ou) * 64 + (v * 8 + j)) * 2 + rr] = acc[i][j];
    }
}

// ---------------------------------------------------------------------------
extern "C" void kernel_launch(void* const* d_in, const int* in_sizes, int n_in,
                              void* d_out, int out_size) {
    const float* in_data = (const float*)d_in[0];
    const float* in_filter = (const float*)d_in[1];
    const float* in_bias = (const float*)d_in[2];
    const float* f[6];
    const float* bb[6];
    for (int l = 0; l < 6; l++) {
        f[l] = (const float*)d_in[3 + 2 * l];
        bb[l] = (const float*)d_in[4 + 2 * l];
    }
    const float* Wd = (const float*)d_in[15];
    float* out = (float*)d_out;

    float *A, *B, *Wt;
    cudaGetSymbolAddress((void**)&A, g_bufA);
    cudaGetSymbolAddress((void**)&B, g_bufB);
    cudaGetSymbolAddress((void**)&Wt, g_bufW);

    constexpr int SMB = 65536;  // 2 buffers x 2 planes x 1024 float4
    cudaFuncSetAttribute(node_mma<2, 1, 32>, cudaFuncAttributeMaxDynamicSharedMemorySize, SMB);
    cudaFuncSetAttribute(node_mma<4, 2, 16>, cudaFuncAttributeMaxDynamicSharedMemorySize, SMB);
    cudaFuncSetAttribute(node_mma<8, 4, 8>, cudaFuncAttributeMaxDynamicSharedMemorySize, SMB);
    cudaFuncSetAttribute(node_mma<8, 8, 4>, cudaFuncAttributeMaxDynamicSharedMemorySize, SMB);
    cudaFuncSetAttribute(node_mma<8, 8, 2>, cudaFuncAttributeMaxDynamicSharedMemorySize, SMB);
    cudaFuncSetAttribute(node_mma<8, 8, 1>, cudaFuncAttributeMaxDynamicSharedMemorySize, SMB);
    cudaFuncSetAttribute(decode, cudaFuncAttributeMaxDynamicSharedMemorySize, 65536);

    prep_w<<<276, 256>>>(f[0], f[1], f[2], f[3], f[4], f[5], Wt);
    first_conv<<<32768, 256>>>(in_data, in_filter, in_bias, A);
    node_mma<2, 1, 32><<<dim3(1024, 4), 256, SMB>>>(A, Wt + (size_t)0 * 32768, bb[0], B);
    node_mma<4, 2, 16><<<dim3(256, 16), 256, SMB>>>(B, Wt + (size_t)4 * 32768, bb[1], A);
    node_mma<8, 4, 8><<<dim3(64, 64), 256, SMB>>>(A, Wt + (size_t)20 * 32768, bb[2], B);
    node_mma<8, 8, 4><<<dim3(16, 64), 256, SMB>>>(B, Wt + (size_t)84 * 32768, bb[3], A);
    node_mma<8, 8, 2><<<dim3(4, 64), 256, SMB>>>(A, Wt + (size_t)148 * 32768, bb[4], B);
    node_mma<8, 8, 1><<<dim3(1, 64), 256, SMB>>>(B, Wt + (size_t)212 * 32768, bb[5], A);
    decode<<<64, 256, 65536>>>(A, Wd, out);
}

// round 14
// speedup vs baseline: 2.0943x; 1.1440x over previous
#include <cuda_runtime.h>
#include <cstdint>

__device__ __forceinline__ uint32_t tf32u(float x) {
    uint32_t u; asm("cvt.rna.tf32.f32 %0, %1;" : "=r"(u) : "f"(x)); return u;
}
__device__ __forceinline__ float uaf(uint32_t u) { return __uint_as_float(u); }
__device__ __forceinline__ uint32_t fau(float f) { return __float_as_uint(f); }

#define MMA_TF32(c, a0, a1, a2, a3, b0, b1)                                   \
    asm volatile(                                                             \
        "mma.sync.aligned.m16n8k8.row.col.f32.tf32.tf32.f32 "                 \
        "{%0,%1,%2,%3},{%4,%5,%6,%7},{%8,%9},{%0,%1,%2,%3};"                  \
        : "+f"((c)[0]), "+f"((c)[1]), "+f"((c)[2]), "+f"((c)[3])              \
        : "r"(a0), "r"(a1), "r"(a2), "r"(a3), "r"(b0), "r"(b1))

// Static scratch (allocations forbidden).
__device__ float g_bufA[33554432];
__device__ float g_bufB[33554432];
__device__ float g_bufW[9043968];  // 276 nodes * 32768 floats (frag-packed hi|lo)

// ---------------------------------------------------------------------------
// First conv: non-overlapping 4x4 patches -> 64 ch + ReLU.
// ---------------------------------------------------------------------------
__global__ void __launch_bounds__(256) first_conv(
    const float* __restrict__ in, const float* __restrict__ fw,
    const float* __restrict__ bias, float* __restrict__ out) {
    __shared__ float sIn[16 * 17];
    __shared__ float sW[1024];
    __shared__ float sB[64];
    const int tid = threadIdx.x;
    for (int j = tid; j < 1024; j += 256) sW[j] = fw[j];
    if (tid < 64) sB[tid] = bias[tid];
    const int P0 = blockIdx.x * 16;
    if (tid < 64) {
        const int pix = tid >> 2, p = tid & 3;
        const int P = P0 + pix, b = P >> 12, x = (P >> 6) & 63, y = P & 63;
        float4 v = *reinterpret_cast<const float4*>(
            in + ((size_t)(b * 256 + 4 * x + p)) * 256 + 4 * y);
        sIn[pix * 17 + p * 4 + 0] = v.x;
        sIn[pix * 17 + p * 4 + 1] = v.y;
        sIn[pix * 17 + p * 4 + 2] = v.z;
        sIn[pix * 17 + p * 4 + 3] = v.w;
    }
    __syncthreads();
    const int c = tid & 63, pq = tid >> 6;
    float acc[4] = {sB[c], sB[c], sB[c], sB[c]};
#pragma unroll
    for (int i = 0; i < 16; i++) {
        const float w = sW[i * 64 + c];
#pragma unroll
        for (int j = 0; j < 4; j++) acc[j] += sIn[(pq * 4 + j) * 17 + i] * w;
    }
#pragma unroll
    for (int j = 0; j < 4; j++)
        out[(size_t)(P0 + pq * 4 + j) * 64 + c] = fmaxf(acc[j], 0.0f);
}

// ---------------------------------------------------------------------------
// W prep: per node, pack W into mma fragment order, tf32 hi/lo split.
// ---------------------------------------------------------------------------
__global__ void __launch_bounds__(256) prep_w(
    const float* __restrict__ f1, const float* __restrict__ f2,
    const float* __restrict__ f3, const float* __restrict__ f4,
    const float* __restrict__ f5, const float* __restrict__ f6,
    float* __restrict__ wt) {
    const int nb = blockIdx.x;  // 0..275
    const float* src;
    int local;
    if (nb < 4)        { src = f1; local = nb; }
    else if (nb < 20)  { src = f2; local = nb - 4; }
    else if (nb < 84)  { src = f3; local = nb - 20; }
    else if (nb < 148) { src = f4; local = nb - 84; }
    else if (nb < 212) { src = f5; local = nb - 148; }
    else               { src = f6; local = nb - 212; }
    src += (size_t)local * 16384;
    float* dst = wt + (size_t)nb * 32768;
    for (int o = threadIdx.x; o < 32768; o += 256) {
        const int p = o >> 14, rem = o & 16383;
        const int sg = rem >> 9, rem2 = rem & 511;
        const int ntp = rem2 >> 7, lane = (rem2 >> 2) & 31, j = o & 3;
        const int tig = lane & 3, grp = lane >> 2;
        const int nt = 2 * ntp + (j >> 1);
        const int k = sg * 8 + tig + (j & 1) * 4;
        const int n = nt * 8 + grp;
        const float w = src[k * 64 + n];
        const float hi = uaf(tf32u(w));
        dst[o] = p ? uaf(tf32u(w - hi)) : hi;
    }
}

// ---------------------------------------------------------------------------
// Tensor node conv via mma.sync m16n8k8 tf32, 3-split.
// Block 128m x 64n, warps 4m x 2n, warp tile 32x32 (2 m16 x 4 n8).
// A smem FRAGMENT-PACKED (as R13).  B now ALSO staged through smem:
// per stage 1024 float4 = [sg4][pl2][off128]; cooperative 4 LDG.128 +
// 4 STS.128 per thread; warp reads are 512B-contiguous LDS.128.
// Frees the 32-reg B double buffer -> no spills under (256,2).
// ---------------------------------------------------------------------------
template <int NU, int NP, int HO>
__global__ void __launch_bounds__(256, 2) node_mma(
    const float* __restrict__ in, const float* __restrict__ wfr,
    const float* __restrict__ bias, float* __restrict__ out) {
    constexpr int C = 64, HI = 2 * HO, WI = 2 * HO, WO = HO;
    constexpr int M = 128 * HO * WO;
    constexpr int BUF4 = 2048;  // A float4s per stage buffer (2 planes x 1024)

    extern __shared__ float smem[];
    float4* s4 = reinterpret_cast<float4*>(smem);   // A: 2 * BUF4
    float4* sB4 = s4 + 2 * BUF4;                    // B: 2 * 1024
    const int tid = threadIdx.x;
    const int lane = tid & 31, warp = tid >> 5;
    const int wm = warp & 3, wn = warp >> 2;
    const int g = lane >> 2, tig = lane & 3;

    const int node = blockIdx.y;
    const int u = node / NU, v = node % NU;
    const int pu = (NP < NU) ? (u >> 1) : u;
    const int pv = (NP < NU) ? (v >> 1) : v;
    const float* inN = in + (size_t)(pu * NP + pv) * 128 * HI * WI * C;
    const float* bN = bias + (size_t)node * 64;
    const float4* wN4 = reinterpret_cast<const float4*>(wfr + (size_t)node * 32768);
    const int m0 = blockIdx.x * 128;

    // ---- A staging geometry (thread owns 4m x 4k) ----
    const int mg = tid >> 3, kslot = tid & 7;
    unsigned aoff[4];
#pragma unroll
    for (int i = 0; i < 4; i++) {
        const int m = m0 + mg * 4 + i;
        const int b = m / (HO * WO);
        const int hw = m - b * HO * WO;
        const int h = hw / WO, w = hw - h * WO;
        aoff[i] = (unsigned)((((b * HI + 2 * h) * WI + 2 * w) * C) + kslot * 4);
    }
    float4 aR[4];
    auto LDGA = [&](int s) {
        const int x = s >> 2, y = (s >> 1) & 1, cb = (s & 1) * 32;
        const unsigned soff = (unsigned)((x * WI + y) * C + cb);
#pragma unroll
        for (int i = 0; i < 4; i++)
            aR[i] = *reinterpret_cast<const float4*>(inN + aoff[i] + soff);
    };

    const int sgW = kslot >> 1;
    const int jW = ((mg >> 1) & 1) + 2 * (kslot & 1);
    const int mtileW = mg >> 2;
    const int lpBase = 16 * (mg & 1);
    auto STSA = [&](int buf) {
        float* base = smem + buf * BUF4 * 4;  // scalar view
#pragma unroll
        for (int i = 0; i < 4; i++) {
            const float vals[4] = {(&aR[i].x)[0], (&aR[i].x)[1],
                                   (&aR[i].x)[2], (&aR[i].x)[3]};
#pragma unroll
            for (int e = 0; e < 4; e++) {
                const int lp = lpBase + 4 * i + e;
                const int lsw = lp ^ sgW ^ (((lp >> 4) & 1) << 2);
                const int f4i = sgW * 256 + mtileW * 32 + lsw;
                const float x = vals[e];
                const float h = uaf(tf32u(x));
                base[f4i * 4 + jW] = h;
                base[(1024 + f4i) * 4 + jW] = uaf(tf32u(x - h));
            }
        }
    };

    // ---- B staging: stage-local layout [sg4][pl2][off128] ----
    const int plB = tid >> 7, offB = tid & 127;
    float4 bR[4];
    auto LDGB = [&](int s) {
#pragma unroll
        for (int j = 0; j < 4; j++)
            bR[j] = wN4[plB * 4096 + (4 * s + j) * 128 + offB];
    };
    auto STSB = [&](int buf) {
        float4* d = sB4 + buf * 1024;
#pragma unroll
        for (int j = 0; j < 4; j++)
            d[j * 256 + plB * 128 + offB] = bR[j];
    };

    float c[2][4][4];
#pragma unroll
    for (int mt = 0; mt < 2; mt++)
#pragma unroll
        for (int nt = 0; nt < 4; nt++)
#pragma unroll
            for (int j = 0; j < 4; j++) c[mt][nt][j] = 0.0f;

    const int Lc = lane ^ (((lane >> 4) & 1) << 2);

    LDGA(0);
    LDGB(0);
    STSA(0);
    STSB(0);
    __syncthreads();

#pragma unroll 1
    for (int s = 0; s < 8; s++) {
        if (s < 7) { LDGA(s + 1); LDGB(s + 1); }
        const float4* Ab = s4 + (s & 1) * BUF4;
        const float4* Bb = sB4 + (s & 1) * 1024;
#pragma unroll
        for (int s8 = 0; s8 < 4; s8++) {
            const int boff = s8 * 256 + wn * 64 + lane;
            const float4 bh0 = Bb[boff];
            const float4 bh1 = Bb[boff + 32];
            const float4 bl0 = Bb[boff + 128];
            const float4 bl1 = Bb[boff + 160];
            const int fb = s8 * 256 + (Lc ^ s8);
#pragma unroll
            for (int mt = 0; mt < 2; mt++) {
                const float4 h4 = Ab[fb + (wm * 2 + mt) * 32];
                const float4 l4 = Ab[1024 + fb + (wm * 2 + mt) * 32];
                const uint32_t ah0 = fau(h4.x), ah1 = fau(h4.y);
                const uint32_t ah2 = fau(h4.z), ah3 = fau(h4.w);
                const uint32_t al0 = fau(l4.x), al1 = fau(l4.y);
                const uint32_t al2 = fau(l4.z), al3 = fau(l4.w);
#pragma unroll
                for (int nt = 0; nt < 4; nt++) {
                    const float4 h = (nt >> 1) ? bh1 : bh0;
                    const float4 l = (nt >> 1) ? bl1 : bl0;
                    uint32_t b0h, b1h, b0l, b1l;
                    if (nt & 1) {
                        b0h = fau(h.z); b1h = fau(h.w);
                        b0l = fau(l.z); b1l = fau(l.w);
                    } else {
                        b0h = fau(h.x); b1h = fau(h.y);
                        b0l = fau(l.x); b1l = fau(l.y);
                    }
                    MMA_TF32(c[mt][nt], ah0, ah1, ah2, ah3, b0h, b1h);
                    MMA_TF32(c[mt][nt], al0, al1, al2, al3, b0h, b1h);
                    MMA_TF32(c[mt][nt], ah0, ah1, ah2, ah3, b0l, b1l);
                }
            }
        }
        if (s < 7) { STSA((s + 1) & 1); STSB((s + 1) & 1); }
        __syncthreads();
    }

    // ---- epilogue: bias + ReLU, float2 stores ----
#pragma unroll
    for (int mt = 0; mt < 2; mt++) {
#pragma unroll
        for (int nt = 0; nt < 4; nt++) {
            const int n0 = wn * 32 + nt * 8 + 2 * tig;
            const float2 bb = *reinterpret_cast<const float2*>(bN + n0);
            const int me = m0 + wm * 32 + mt * 16 + g;
            float* pe = out + ((size_t)node * M + me) * 64 + n0;
            float* po = pe + 8 * 64;
            *reinterpret_cast<float2*>(pe) = make_float2(
                fmaxf(c[mt][nt][0] + bb.x, 0.0f), fmaxf(c[mt][nt][1] + bb.y, 0.0f));
            *reinterpret_cast<float2*>(po) = make_float2(
                fmaxf(c[mt][nt][2] + bb.x, 0.0f), fmaxf(c[mt][nt][3] + bb.y, 0.0f));
        }
    }
}

// ---------------------------------------------------------------------------
// Decode: per node out[u,v,b,r,k] = sum_c feats[u,v,b,c]*Wd[u,v,r,c,k].
// ---------------------------------------------------------------------------
__global__ void __launch_bounds__(256) decode(
    const float* __restrict__ feats, const float* __restrict__ Wd,
    float* __restrict__ out) {
    extern __shared__ float dsm[];
    float* sF = dsm;
    float* sWd = dsm + 8192;
    const int tid = threadIdx.x;
    const int node = blockIdx.x, u = node >> 3, v = node & 7;
    const float* fN = feats + (size_t)node * 8192;
    const float* wN = Wd + (size_t)node * 8192;
#pragma unroll
    for (int j = 0; j < 8; j++) {
        const int f4 = tid + j * 256;
        reinterpret_cast<float4*>(sF)[f4] = reinterpret_cast<const float4*>(fN)[f4];
        reinterpret_cast<float4*>(sWd)[f4] = reinterpret_cast<const float4*>(wN)[f4];
    }
    __syncthreads();
    const int bg = tid >> 4, ng = tid & 15, rr = ng >> 3, kk0 = (ng & 7) * 8;
    float acc[8][8];
#pragma unroll
    for (int i = 0; i < 8; i++)
#pragma unroll
        for (int j = 0; j < 8; j++) acc[i][j] = 0.0f;
#pragma unroll 4
    for (int k = 0; k < 64; k++) {
        const float4 w0 = *reinterpret_cast<const float4*>(sWd + rr * 4096 + k * 64 + kk0);
        const float4 w1 = *reinterpret_cast<const float4*>(sWd + rr * 4096 + k * 64 + kk0 + 4);
        const float wv[8] = {w0.x, w0.y, w0.z, w0.w, w1.x, w1.y, w1.z, w1.w};
#pragma unroll
        for (int i = 0; i < 8; i++) {
            const float a = sF[(bg * 8 + i) * 64 + k];
#pragma unroll
            for (int j = 0; j < 8; j++) acc[i][j] += a * wv[j];
        }
    }
    const int ou = ng & 7;
#pragma unroll
    for (int i = 0; i < 8; i++) {
        const int b = bg * 8 + i;
#pragma unroll
        for (int j = 0; j < 8; j++)
            out[(((size_t)b * 64 + u * 8 + ou) * 64 + (v * 8 + j)) * 2 + rr] = acc[i][j];
    }
}

// ---------------------------------------------------------------------------
extern "C" void kernel_launch(void* const* d_in, const int* in_sizes, int n_in,
                              void* d_out, int out_size) {
    const float* in_data = (const float*)d_in[0];
    const float* in_filter = (const float*)d_in[1];
    const float* in_bias = (const float*)d_in[2];
    const float* f[6];
    const float* bb[6];
    for (int l = 0; l < 6; l++) {
        f[l] = (const float*)d_in[3 + 2 * l];
        bb[l] = (const float*)d_in[4 + 2 * l];
    }
    const float* Wd = (const float*)d_in[15];
    float* out = (float*)d_out;

    float *A, *B, *Wt;
    cudaGetSymbolAddress((void**)&A, g_bufA);
    cudaGetSymbolAddress((void**)&B, g_bufB);
    cudaGetSymbolAddress((void**)&Wt, g_bufW);

    constexpr int SMB = (4096 + 2048) * 16;  // 98,304 B (A 64K + B 32K)
    cudaFuncSetAttribute(node_mma<2, 1, 32>, cudaFuncAttributeMaxDynamicSharedMemorySize, SMB);
    cudaFuncSetAttribute(node_mma<4, 2, 16>, cudaFuncAttributeMaxDynamicSharedMemorySize, SMB);
    cudaFuncSetAttribute(node_mma<8, 4, 8>, cudaFuncAttributeMaxDynamicSharedMemorySize, SMB);
    cudaFuncSetAttribute(node_mma<8, 8, 4>, cudaFuncAttributeMaxDynamicSharedMemorySize, SMB);
    cudaFuncSetAttribute(node_mma<8, 8, 2>, cudaFuncAttributeMaxDynamicSharedMemorySize, SMB);
    cudaFuncSetAttribute(node_mma<8, 8, 1>, cudaFuncAttributeMaxDynamicSharedMemorySize, SMB);
    cudaFuncSetAttribute(decode, cudaFuncAttributeMaxDynamicSharedMemorySize, 65536);

    prep_w<<<276, 256>>>(f[0], f[1], f[2], f[3], f[4], f[5], Wt);
    first_conv<<<32768, 256>>>(in_data, in_filter, in_bias, A);
    node_mma<2, 1, 32><<<dim3(1024, 4), 256, SMB>>>(A, Wt + (size_t)0 * 32768, bb[0], B);
    node_mma<4, 2, 16><<<dim3(256, 16), 256, SMB>>>(B, Wt + (size_t)4 * 32768, bb[1], A);
    node_mma<8, 4, 8><<<dim3(64, 64), 256, SMB>>>(A, Wt + (size_t)20 * 32768, bb[2], B);
    node_mma<8, 8, 4><<<dim3(16, 64), 256, SMB>>>(B, Wt + (size_t)84 * 32768, bb[3], A);
    node_mma<8, 8, 2><<<dim3(4, 64), 256, SMB>>>(A, Wt + (size_t)148 * 32768, bb[4], B);
    node_mma<8, 8, 1><<<dim3(1, 64), 256, SMB>>>(B, Wt + (size_t)212 * 32768, bb[5], A);
    decode<<<64, 256, 65536>>>(A, Wd, out);
}